// round 14
// baseline (speedup 1.0000x reference)
#include <cuda_runtime.h>
#include <cuda_fp16.h>
#include <mma.h>
#include <math.h>

using namespace nvcuda;

constexpr int NN   = 50000;
constexpr int EE   = 800000;
constexpr int DIN  = 128;
constexpr int DE   = 16;
constexpr int C    = 64;
constexpr int HID  = 256;
constexpr float NEG = 0.2f;

constexpr int SCAT_BLOCKS = (EE + 255) / 256;        // 3125
constexpr int ROW_BLOCKS  = (NN + 63) / 64;          // 782

// ---------------- device scratch --------------------------------------------
__device__ int    g_cnt[NN];          // zero at load; re-zeroed by scan each run
__device__ int    g_rowptr[NN + 1];
__device__ int    g_cursor[NN];
__device__ int2   g_csr_se[EE];       // (src, eid) per CSR slot
__device__ __half g_ewe1[(size_t)EE * 64];   // layer-1 e@We, fp16
__device__ __half g_ewe2[(size_t)EE * 64];   // layer-2 e@We, fp16
__device__ float  g_xlr[NN * 128];    // cols 0..63 = xl, 64..127 = xr
__device__ float  g_h[NN * C];
__device__ float  g_h2[NN * C];
__device__ float  g_P12[NN * 512];    // cols 0..255 = P1, 256..511 = P2
__device__ float  g_Wp1[DIN * 128];
__device__ float  g_Wp2[C * 128];
__device__ float  g_WpC[C * 512];
__device__ float  g_Wep[DE * 128];    // [We1 | We2]
__device__ float  g_bp1[128];
__device__ float  g_bp2[128];

__device__ __forceinline__ float lrelu(float x) { return x > 0.f ? x : NEG * x; }
__device__ __forceinline__ float eluf(float x)  { return x > 0.f ? x : __expf(x) - 1.f; }

typedef unsigned long long ull;
__device__ __forceinline__ ull pack2(float lo, float hi) {
    ull r;
    asm("mov.b64 %0, {%1, %2};" : "=l"(r) : "f"(lo), "f"(hi));
    return r;
}
__device__ __forceinline__ void unpack2(ull v, float& lo, float& hi) {
    asm("mov.b64 {%0, %1}, %2;" : "=f"(lo), "=f"(hi) : "l"(v));
}
__device__ __forceinline__ ull ffma2(ull a, ull b, ull c) {
    ull d;
    asm("fma.rn.f32x2 %0, %1, %2, %3;" : "=l"(d) : "l"(a), "l"(b), "l"(c));
    return d;
}
__device__ __forceinline__ ull add2(ull a, ull b) {
    ull d;
    asm("add.rn.f32x2 %0, %1, %2;" : "=l"(d) : "l"(a), "l"(b));
    return d;
}
__device__ __forceinline__ ull mul2(ull a, ull b) {
    ull d;
    asm("mul.rn.f32x2 %0, %1, %2;" : "=l"(d) : "l"(a), "l"(b));
    return d;
}

// ---------------- launch 1: pack weights + degree histogram ------------------
__global__ void prep_kernel(const float* __restrict__ W1l, const float* __restrict__ W1r,
                            const float* __restrict__ b1l, const float* __restrict__ b1r,
                            const float* __restrict__ W2l, const float* __restrict__ W2r,
                            const float* __restrict__ b2l, const float* __restrict__ b2r,
                            const float* __restrict__ We1, const float* __restrict__ We2,
                            const float* __restrict__ Cw1,
                            const int* __restrict__ ei) {
    int i = blockIdx.x * blockDim.x + threadIdx.x;
    if (i < EE) atomicAdd(&g_cnt[ei[EE + i]], 1);   // g_cnt zeroed by prior scan
    if (i < DIN * 128) {
        int k = i >> 7, c = i & 127;
        g_Wp1[i] = (c < 64) ? W1l[k * 64 + c] : W1r[k * 64 + c - 64];
    }
    if (i < DE * 128) {
        int k = i >> 7, c = i & 127;
        g_Wep[i] = (c < 64) ? We1[k * 64 + c] : We2[k * 64 + c - 64];
    }
    int j = i - DIN * 128;
    if (j >= 0 && j < C * 128) {
        int k = j >> 7, c = j & 127;
        g_Wp2[j] = (c < 64) ? W2l[k * 64 + c] : W2r[k * 64 + c - 64];
    }
    int l = i - DIN * 128 - C * 128;
    if (l >= 0 && l < C * 512) {
        int k = l >> 9, c = l & 511;
        g_WpC[l] = (c < 256) ? Cw1[k * 256 + c] : Cw1[(64 + k) * 256 + c - 256];
    }
    if (i < 128) {
        g_bp1[i] = (i < 64) ? b1l[i] : b1r[i - 64];
        g_bp2[i] = (i < 64) ? b2l[i] : b2r[i - 64];
    }
}

// ---------------- launch 2: scan (and re-zero g_cnt for the next run) --------
__global__ void csr_scan_kernel() {
    __shared__ int wsum[32];
    int t = threadIdx.x, lane = t & 31, wid = t >> 5;
    int running = 0;
    const int CH = (NN + 1023) / 1024;
    for (int c = 0; c < CH; c++) {
        int i = c * 1024 + t;
        int v = 0;
        if (i < NN) { v = g_cnt[i]; g_cnt[i] = 0; }
        int s = v;
        #pragma unroll
        for (int o = 1; o < 32; o <<= 1) {
            int u = __shfl_up_sync(0xffffffffu, s, o);
            if (lane >= o) s += u;
        }
        if (lane == 31) wsum[wid] = s;
        __syncthreads();
        if (wid == 0) {
            int ws = wsum[lane];
            #pragma unroll
            for (int o = 1; o < 32; o <<= 1) {
                int u = __shfl_up_sync(0xffffffffu, ws, o);
                if (lane >= o) ws += u;
            }
            wsum[lane] = ws;
        }
        __syncthreads();
        int excl = running + (wid ? wsum[wid - 1] : 0) + s - v;
        if (i < NN) { g_rowptr[i] = excl; g_cursor[i] = excl; }
        running += wsum[31];
        __syncthreads();
    }
    if (t == 0) g_rowptr[NN] = running;
}

// ---------------- tf32 WMMA GEMM body ----------------------------------------
constexpr int LDA = 40;
constexpr int LDB = 72;
constexpr int LDO = 72;
constexpr int SM_GEMM = 64 * LDA + 32 * LDB;                      // 4864

__device__ void gemm_body(float* sm,
                          const float* __restrict__ X,
                          const float* __restrict__ W,
                          const float* __restrict__ bias,
                          float* __restrict__ Cmat,
                          int n, int K, int Cout,
                          int rowTile, int colTile) {
    float* As = sm;
    float* Bs = sm + 64 * LDA;
    float* sOut = sm;

    int tid = threadIdx.x;
    int warpId = tid >> 5;
    int rowBase = rowTile * 64;
    int colB    = colTile * 64;
    int warpRow = (warpId & 3) * 16;
    int warpCol = (warpId >> 2) * 32;

    wmma::fragment<wmma::accumulator, 16, 16, 8, float> acc0, acc1;
    wmma::fill_fragment(acc0, 0.f);
    wmma::fill_fragment(acc1, 0.f);

    for (int kt = 0; kt < K; kt += 32) {
        #pragma unroll
        for (int f = tid; f < 512; f += 256) {
            int row = f >> 3, kq = f & 7;
            float4 v = make_float4(0.f, 0.f, 0.f, 0.f);
            if (rowBase + row < n)
                v = *(const float4*)&X[(size_t)(rowBase + row) * K + kt + kq * 4];
            float* d = &As[row * LDA + kq * 4];
            d[0] = wmma::__float_to_tf32(v.x);
            d[1] = wmma::__float_to_tf32(v.y);
            d[2] = wmma::__float_to_tf32(v.z);
            d[3] = wmma::__float_to_tf32(v.w);
        }
        #pragma unroll
        for (int f = tid; f < 512; f += 256) {
            int row = f >> 4, cq = f & 15;
            float4 v = *(const float4*)&W[(size_t)(kt + row) * Cout + colB + cq * 4];
            float* d = &Bs[row * LDB + cq * 4];
            d[0] = wmma::__float_to_tf32(v.x);
            d[1] = wmma::__float_to_tf32(v.y);
            d[2] = wmma::__float_to_tf32(v.z);
            d[3] = wmma::__float_to_tf32(v.w);
        }
        __syncthreads();
        #pragma unroll
        for (int kk = 0; kk < 32; kk += 8) {
            wmma::fragment<wmma::matrix_a, 16, 16, 8, wmma::precision::tf32, wmma::row_major> a;
            wmma::fragment<wmma::matrix_b, 16, 16, 8, wmma::precision::tf32, wmma::row_major> b0, b1;
            wmma::load_matrix_sync(a, &As[warpRow * LDA + kk], LDA);
            wmma::load_matrix_sync(b0, &Bs[kk * LDB + warpCol], LDB);
            wmma::load_matrix_sync(b1, &Bs[kk * LDB + warpCol + 16], LDB);
            wmma::mma_sync(acc0, a, b0, acc0);
            wmma::mma_sync(acc1, a, b1, acc1);
        }
        __syncthreads();
    }

    wmma::store_matrix_sync(&sOut[warpRow * LDO + warpCol],      acc0, LDO, wmma::mem_row_major);
    wmma::store_matrix_sync(&sOut[warpRow * LDO + warpCol + 16], acc1, LDO, wmma::mem_row_major);
    __syncthreads();
    #pragma unroll
    for (int f = tid; f < 1024; f += 256) {
        int row = f >> 4, cq = f & 15;
        if (rowBase + row < n) {
            float4 v = *(float4*)&sOut[row * LDO + cq * 4];
            if (bias) {
                float4 b = *(const float4*)&bias[colB + cq * 4];
                v.x += b.x; v.y += b.y; v.z += b.z; v.w += b.w;
            }
            *(float4*)&Cmat[(size_t)(rowBase + row) * Cout + colB + cq * 4] = v;
        }
    }
}

__global__ void gemm_tf32_kernel(const float* __restrict__ X,
                                 const float* __restrict__ W,
                                 const float* __restrict__ bias,
                                 float* __restrict__ Cmat,
                                 int n, int K, int Cout) {
    __shared__ float sm[SM_GEMM];
    gemm_body(sm, X, W, bias, Cmat, n, K, Cout, blockIdx.x, blockIdx.y);
}

// ---------------- launch 3: CSR scatter + layer-1 GEMM (fused) ---------------
__global__ void scatter_gemm_kernel(const int* __restrict__ ei,
                                    const float* __restrict__ X) {
    __shared__ float sm[SM_GEMM];
    if (blockIdx.x < SCAT_BLOCKS) {
        int e = blockIdx.x * blockDim.x + threadIdx.x;
        if (e >= EE) return;
        int dst = ei[EE + e];
        int pos = atomicAdd(&g_cursor[dst], 1);
        g_csr_se[pos] = make_int2(ei[e], e);
    } else {
        int gb = blockIdx.x - SCAT_BLOCKS;
        int colTile = gb / ROW_BLOCKS;
        int rowTile = gb - colTile * ROW_BLOCKS;
        gemm_body(sm, X, g_Wp1, g_bp1, g_xlr, NN, DIN, 128, rowTile, colTile);
    }
}

// ---------------- launch 4: ewe — register FFMA2, warp per edge pair ---------
// lane owns cols (2l,2l+1) of We1 and of We2 (64 weight regs); ea via uniform
// L1-broadcast float4; 32 FFMA2/edge; contiguous half2 stores. No smem.
__global__ __launch_bounds__(128)
void ewe_kernel(const float* __restrict__ eattr) {
    int lane = threadIdx.x & 31;
    ull w1[DE], w2[DE];
    #pragma unroll
    for (int k = 0; k < DE; k++) {
        w1[k] = pack2(g_Wep[k * 128 + 2 * lane], g_Wep[k * 128 + 2 * lane + 1]);
        w2[k] = pack2(g_Wep[k * 128 + 64 + 2 * lane], g_Wep[k * 128 + 64 + 2 * lane + 1]);
    }
    const float4* EA = (const float4*)eattr;
    unsigned* out1 = (unsigned*)g_ewe1;   // 32 half2 per edge row
    unsigned* out2 = (unsigned*)g_ewe2;

    int warpGid = (blockIdx.x * blockDim.x + threadIdx.x) >> 5;
    int warpsTotal = (gridDim.x * blockDim.x) >> 5;
    const int NPAIR = EE / 2;

    for (int pr = warpGid; pr < NPAIR; pr += warpsTotal) {
        int e0 = 2 * pr, e1 = 2 * pr + 1;
        float ea0[DE], ea1[DE];
        *(float4*)&ea0[0]  = EA[(size_t)e0 * 4 + 0];
        *(float4*)&ea0[4]  = EA[(size_t)e0 * 4 + 1];
        *(float4*)&ea0[8]  = EA[(size_t)e0 * 4 + 2];
        *(float4*)&ea0[12] = EA[(size_t)e0 * 4 + 3];
        *(float4*)&ea1[0]  = EA[(size_t)e1 * 4 + 0];
        *(float4*)&ea1[4]  = EA[(size_t)e1 * 4 + 1];
        *(float4*)&ea1[8]  = EA[(size_t)e1 * 4 + 2];
        *(float4*)&ea1[12] = EA[(size_t)e1 * 4 + 3];
        ull a10 = 0, a20 = 0, a11 = 0, a21 = 0;
        #pragma unroll
        for (int k = 0; k < DE; k++) {
            ull s0 = pack2(ea0[k], ea0[k]);
            ull s1 = pack2(ea1[k], ea1[k]);
            a10 = ffma2(s0, w1[k], a10);
            a20 = ffma2(s0, w2[k], a20);
            a11 = ffma2(s1, w1[k], a11);
            a21 = ffma2(s1, w2[k], a21);
        }
        float lo, hi;
        unpack2(a10, lo, hi); __half2 h10 = __floats2half2_rn(lo, hi);
        unpack2(a20, lo, hi); __half2 h20 = __floats2half2_rn(lo, hi);
        unpack2(a11, lo, hi); __half2 h11 = __floats2half2_rn(lo, hi);
        unpack2(a21, lo, hi); __half2 h21 = __floats2half2_rn(lo, hi);
        out1[(size_t)e0 * 32 + lane] = *(unsigned*)&h10;
        out2[(size_t)e0 * 32 + lane] = *(unsigned*)&h20;
        out1[(size_t)e1 * 32 + lane] = *(unsigned*)&h11;
        out2[(size_t)e1 * 32 + lane] = *(unsigned*)&h21;
    }
}

// ---------------- fused GAT layer: warp/node, fp16 ewe by eid, 2-edge unroll -
__global__ __launch_bounds__(256)
void gat_layer_kernel(const __half* __restrict__ ewe,
                      const float* __restrict__ att,
                      const float* __restrict__ bias,
                      float* __restrict__ outbuf,
                      int doElu) {
    int lane = threadIdx.x & 31;
    int node = (blockIdx.x * blockDim.x + threadIdx.x) >> 5;
    if (node >= NN) return;

    float2 a2 = ((const float2*)att)[lane];
    float2 b2 = ((const float2*)bias)[lane];
    const float2* xlr2 = (const float2*)g_xlr;
    const __half2* ewe2 = (const __half2*)ewe;

    int start = g_rowptr[node], end = g_rowptr[node + 1];
    float2 rf  = xlr2[node * 64 + 32 + lane];
    float2 vSf = xlr2[node * 64 + lane];
    ull r2  = pack2(rf.x, rf.y);
    ull vS2 = pack2(vSf.x, vSf.y);

    float amax = -INFINITY, den = 0.f;
    ull acc = 0, wsum = 0;

    ull vA = 0, wA = 0, vB = 0, wB = 0;
    if (start < end) {
        int2 se = g_csr_se[start];
        float2 t = xlr2[se.x * 64 + lane];            vA = pack2(t.x, t.y);
        float2 u = __half22float2(ewe2[(size_t)se.y * 32 + lane]); wA = pack2(u.x, u.y);
    }
    if (start + 1 < end) {
        int2 se = g_csr_se[start + 1];
        float2 t = xlr2[se.x * 64 + lane];            vB = pack2(t.x, t.y);
        float2 u = __half22float2(ewe2[(size_t)se.y * 32 + lane]); wB = pack2(u.x, u.y);
    }

    int p = start;
    for (; p + 1 < end; p += 2) {
        ull v0 = vA, w0 = wA, v1 = vB, w1 = wB;
        if (p + 2 < end) {
            int2 se = g_csr_se[p + 2];
            float2 t = xlr2[se.x * 64 + lane];            vA = pack2(t.x, t.y);
            float2 u = __half22float2(ewe2[(size_t)se.y * 32 + lane]); wA = pack2(u.x, u.y);
        }
        if (p + 3 < end) {
            int2 se = g_csr_se[p + 3];
            float2 t = xlr2[se.x * 64 + lane];            vB = pack2(t.x, t.y);
            float2 u = __half22float2(ewe2[(size_t)se.y * 32 + lane]); wB = pack2(u.x, u.y);
        }
        wsum = add2(wsum, add2(w0, w1));
        ull m0 = add2(add2(v0, r2), w0);
        ull m1 = add2(add2(v1, r2), w1);
        float m0x, m0y, m1x, m1y;
        unpack2(m0, m0x, m0y);
        unpack2(m1, m1x, m1y);
        float pk0 = lrelu(m0x) * a2.x + lrelu(m0y) * a2.y;
        float pk1 = lrelu(m1x) * a2.x + lrelu(m1y) * a2.y;
        #pragma unroll
        for (int o = 16; o; o >>= 1) {
            pk0 += __shfl_xor_sync(0xffffffffu, pk0, o);
            pk1 += __shfl_xor_sync(0xffffffffu, pk1, o);
        }
        float pm = fmaxf(pk0, pk1);
        if (pm > amax) {
            float f = __expf(amax - pm);
            den *= f;
            acc = mul2(acc, pack2(f, f));
            amax = pm;
        }
        float e0 = __expf(pk0 - amax), e1 = __expf(pk1 - amax);
        den += e0 + e1;
        acc = ffma2(pack2(e0, e0), v0, acc);
        acc = ffma2(pack2(e1, e1), v1, acc);
    }
    if (p < end) {   // odd tail
        wsum = add2(wsum, wA);
        ull m0 = add2(add2(vA, r2), wA);
        float m0x, m0y;
        unpack2(m0, m0x, m0y);
        float pk0 = lrelu(m0x) * a2.x + lrelu(m0y) * a2.y;
        #pragma unroll
        for (int o = 16; o; o >>= 1) pk0 += __shfl_xor_sync(0xffffffffu, pk0, o);
        if (pk0 > amax) {
            float f = __expf(amax - pk0);
            den *= f;
            acc = mul2(acc, pack2(f, f));
            amax = pk0;
        }
        float e0 = __expf(pk0 - amax);
        den += e0;
        acc = ffma2(pack2(e0, e0), vA, acc);
    }

    // self loop: ewe_self = mean(ewe) over incoming edges (linearity of @We)
    float invdeg = 1.f / fmaxf((float)(end - start), 1.f);
    ull mS = add2(add2(vS2, r2), mul2(wsum, pack2(invdeg, invdeg)));
    float msx, msy;
    unpack2(mS, msx, msy);
    float pS = lrelu(msx) * a2.x + lrelu(msy) * a2.y;
    #pragma unroll
    for (int o = 16; o; o >>= 1) pS += __shfl_xor_sync(0xffffffffu, pS, o);
    if (pS > amax) {
        float f = __expf(amax - pS);
        den *= f;
        acc = mul2(acc, pack2(f, f));
        amax = pS;
    }
    float eS = __expf(pS - amax);
    den += eS;
    acc = ffma2(pack2(eS, eS), vS2, acc);

    float inv = 1.f / den;
    float accx, accy;
    unpack2(acc, accx, accy);
    float ox = accx * inv + b2.x;
    float oy = accy * inv + b2.y;
    if (doElu) { ox = eluf(ox); oy = eluf(oy); }
    ((float2*)outbuf)[node * 32 + lane] = make_float2(ox, oy);
}

// ---------------- edge classifier: warp per edge PAIR, fp16 weights ----------
__global__ __launch_bounds__(128)
void classifier_kernel(const float* __restrict__ eattr,
                       const int* __restrict__ ei,
                       const float* __restrict__ Cw1c,   // [16][256]
                       const float* __restrict__ Cb1,
                       const float* __restrict__ Cw2,
                       const float* __restrict__ Cb2,
                       float* __restrict__ out) {
    int lane = threadIdx.x & 31;
    int c0 = 4 * lane;
    __half2 wh[DE][4];
    #pragma unroll
    for (int k = 0; k < DE; k++) {
        float4 A = *(const float4*)&Cw1c[k * HID + c0];
        float4 B = *(const float4*)&Cw1c[k * HID + 128 + c0];
        wh[k][0] = __floats2half2_rn(A.x, A.y);
        wh[k][1] = __floats2half2_rn(A.z, A.w);
        wh[k][2] = __floats2half2_rn(B.x, B.y);
        wh[k][3] = __floats2half2_rn(B.z, B.w);
    }
    float4 b0 = *(const float4*)&Cb1[c0];
    float4 b1 = *(const float4*)&Cb1[128 + c0];
    float4 c20 = *(const float4*)&Cw2[c0];
    float4 c21 = *(const float4*)&Cw2[128 + c0];
    float cb2 = Cb2[0];

    const float4* P  = (const float4*)g_P12;
    const float4* EA = (const float4*)eattr;
    int pairGid = (blockIdx.x * blockDim.x + threadIdx.x) >> 5;
    int pairsTotal = (gridDim.x * blockDim.x) >> 5;
    const int NPAIR = EE / 2;

    for (int pr = pairGid; pr < NPAIR; pr += pairsTotal) {
        int e0 = 2 * pr, e1 = 2 * pr + 1;
        int src0 = ei[e0], dst0 = ei[EE + e0];
        int src1 = ei[e1], dst1 = ei[EE + e1];
        float4 p1a0 = P[(size_t)src0 * 128 + lane];
        float4 p1b0 = P[(size_t)src0 * 128 + 32 + lane];
        float4 p2a0 = P[(size_t)dst0 * 128 + 64 + lane];
        float4 p2b0 = P[(size_t)dst0 * 128 + 96 + lane];
        float4 p1a1 = P[(size_t)src1 * 128 + lane];
        float4 p1b1 = P[(size_t)src1 * 128 + 32 + lane];
        float4 p2a1 = P[(size_t)dst1 * 128 + 64 + lane];
        float4 p2b1 = P[(size_t)dst1 * 128 + 96 + lane];
        __half2 x0 = __float2half2_rn(0.f), x1 = x0, x2 = x0, x3 = x0;
        __half2 y0 = x0, y1 = x0, y2 = x0, y3 = x0;
        #pragma unroll
        for (int kq = 0; kq < 4; kq++) {
            float4 ea0 = EA[(size_t)e0 * 4 + kq];
            float4 ea1 = EA[(size_t)e1 * 4 + kq];
            const float* e0p = (const float*)&ea0;
            const float* e1p = (const float*)&ea1;
            #pragma unroll
            for (int j = 0; j < 4; j++) {
                int k = kq * 4 + j;
                __half2 s0 = __float2half2_rn(e0p[j]);
                __half2 s1 = __float2half2_rn(e1p[j]);
                x0 = __hfma2(s0, wh[k][0], x0);
                x1 = __hfma2(s0, wh[k][1], x1);
                x2 = __hfma2(s0, wh[k][2], x2);
                x3 = __hfma2(s0, wh[k][3], x3);
                y0 = __hfma2(s1, wh[k][0], y0);
                y1 = __hfma2(s1, wh[k][1], y1);
                y2 = __hfma2(s1, wh[k][2], y2);
                y3 = __hfma2(s1, wh[k][3], y3);
            }
        }
        float2 f0 = __half22float2(x0), f1 = __half22float2(x1);
        float2 f2 = __half22float2(x2), f3 = __half22float2(x3);
        float2 g0 = __half22float2(y0), g1 = __half22float2(y1);
        float2 g2 = __half22float2(y2), g3 = __half22float2(y3);
        float acc0 =
              eluf(f0.x + p1a0.x + p2a0.x + b0.x) * c20.x
            + eluf(f0.y + p1a0.y + p2a0.y + b0.y) * c20.y
            + eluf(f1.x + p1a0.z + p2a0.z + b0.z) * c20.z
            + eluf(f1.y + p1a0.w + p2a0.w + b0.w) * c20.w
            + eluf(f2.x + p1b0.x + p2b0.x + b1.x) * c21.x
            + eluf(f2.y + p1b0.y + p2b0.y + b1.y) * c21.y
            + eluf(f3.x + p1b0.z + p2b0.z + b1.z) * c21.z
            + eluf(f3.y + p1b0.w + p2b0.w + b1.w) * c21.w;
        float acc1 =
              eluf(g0.x + p1a1.x + p2a1.x + b0.x) * c20.x
            + eluf(g0.y + p1a1.y + p2a1.y + b0.y) * c20.y
            + eluf(g1.x + p1a1.z + p2a1.z + b0.z) * c20.z
            + eluf(g1.y + p1a1.w + p2a1.w + b0.w) * c20.w
            + eluf(g2.x + p1b1.x + p2b1.x + b1.x) * c21.x
            + eluf(g2.y + p1b1.y + p2b1.y + b1.y) * c21.y
            + eluf(g3.x + p1b1.z + p2b1.z + b1.z) * c21.z
            + eluf(g3.y + p1b1.w + p2b1.w + b1.w) * c21.w;
        #pragma unroll
        for (int o = 16; o; o >>= 1) {
            acc0 += __shfl_xor_sync(0xffffffffu, acc0, o);
            acc1 += __shfl_xor_sync(0xffffffffu, acc1, o);
        }
        if (lane == 0) {
            out[e0] = acc0 + cb2;
            out[e1] = acc1 + cb2;
        }
    }
}

// ---------------- host orchestration ----------------------------------------
static inline int ceil_div(int a, int b) { return (a + b - 1) / b; }

extern "C" void kernel_launch(void* const* d_in, const int* in_sizes, int n_in,
                              void* d_out, int out_size) {
    const float* x     = (const float*)d_in[0];
    const float* eattr = (const float*)d_in[1];
    const float* W1l   = (const float*)d_in[2];
    const float* b1l   = (const float*)d_in[3];
    const float* W1r   = (const float*)d_in[4];
    const float* b1r   = (const float*)d_in[5];
    const float* We1   = (const float*)d_in[6];
    const float* att1  = (const float*)d_in[7];
    const float* bias1 = (const float*)d_in[8];
    const float* W2l   = (const float*)d_in[9];
    const float* b2l   = (const float*)d_in[10];
    const float* W2r   = (const float*)d_in[11];
    const float* b2r   = (const float*)d_in[12];
    const float* We2   = (const float*)d_in[13];
    const float* att2  = (const float*)d_in[14];
    const float* bias2 = (const float*)d_in[15];
    // d_in[16..19] (Aw1/Ab1/Aw2/Ab2): softmax over a single column == 1 -> unused
    const float* Cw1   = (const float*)d_in[20];
    const float* Cb1   = (const float*)d_in[21];
    const float* Cw2   = (const float*)d_in[22];
    const float* Cb2   = (const float*)d_in[23];
    const int*   ei    = (const int*)  d_in[24];
    float* out = (float*)d_out;

    float *d_h, *d_h2, *d_P12, *d_Wp2, *d_WpC, *d_bp2, *d_xlr;
    __half *d_ewe1, *d_ewe2;
    cudaGetSymbolAddress((void**)&d_h,    g_h);
    cudaGetSymbolAddress((void**)&d_h2,   g_h2);
    cudaGetSymbolAddress((void**)&d_P12,  g_P12);
    cudaGetSymbolAddress((void**)&d_Wp2,  g_Wp2);
    cudaGetSymbolAddress((void**)&d_WpC,  g_WpC);
    cudaGetSymbolAddress((void**)&d_bp2,  g_bp2);
    cudaGetSymbolAddress((void**)&d_xlr,  g_xlr);
    cudaGetSymbolAddress((void**)&d_ewe1, g_ewe1);
    cudaGetSymbolAddress((void**)&d_ewe2, g_ewe2);

    const int TB = 256;
    int gatBlocks = ceil_div(NN * 32, TB);

    // 1: pack weights + histogram
    prep_kernel<<<ceil_div(EE, TB), TB>>>(W1l, W1r, b1l, b1r, W2l, W2r, b2l, b2r,
                                          We1, We2, Cw1, ei);
    // 2: scan (+ re-zero g_cnt)
    csr_scan_kernel<<<1, 1024>>>();
    // 3: CSR scatter + layer-1 GEMM fused
    scatter_gemm_kernel<<<SCAT_BLOCKS + 2 * ROW_BLOCKS, 256>>>(ei, x);
    // 4: ewe register kernel  (ncu capture slot)
    ewe_kernel<<<2368, 128>>>(eattr);
    // 5: GAT layer 1
    gat_layer_kernel<<<gatBlocks, TB>>>(d_ewe1, att1, bias1, d_h, 1);
    // 6-7: layer 2
    gemm_tf32_kernel<<<dim3(ROW_BLOCKS, 2), 256>>>(d_h, d_Wp2, d_bp2, d_xlr, NN, C, 128);
    gat_layer_kernel<<<gatBlocks, TB>>>(d_ewe2, att2, bias2, d_h2, 0);
    // 8-9: classifier
    gemm_tf32_kernel<<<dim3(ROW_BLOCKS, 8), 256>>>(d_h2, d_WpC, nullptr, d_P12, NN, C, 512);
    classifier_kernel<<<2368, 128>>>(eattr, ei, Cw1 + 2 * C * HID, Cb1, Cw2, Cb2, out);
}

// round 15
// speedup vs baseline: 1.1540x; 1.1540x over previous
#include <cuda_runtime.h>
#include <cuda_fp16.h>
#include <mma.h>
#include <math.h>

using namespace nvcuda;

constexpr int NN   = 50000;
constexpr int EE   = 800000;
constexpr int DIN  = 128;
constexpr int DE   = 16;
constexpr int C    = 64;
constexpr int HID  = 256;
constexpr float NEG = 0.2f;

constexpr int SCAT_BLOCKS = (EE + 255) / 256;        // 3125
constexpr int ROW_BLOCKS  = (NN + 63) / 64;          // 782
constexpr int EWE_BLOCKS  = EE / 64;                 // 12500 (exact)
constexpr int SCAN_BLOCKS = (NN + 1023) / 1024;      // 49

// ---------------- device scratch --------------------------------------------
__device__ int    g_cnt[NN];          // zero at load; re-zeroed by scan_final
__device__ int    g_rowptr[NN + 1];
__device__ int    g_cursor[NN];
__device__ int    g_bsum[64];
__device__ int    g_boff[64];
__device__ int2   g_csr_se[EE];       // (src, eid) per CSR slot
__device__ __half g_ewe1[(size_t)EE * 64];   // layer-1 e@We, fp16
__device__ __half g_ewe2[(size_t)EE * 64];   // layer-2 e@We, fp16
__device__ float  g_xlr[NN * 128];    // cols 0..63 = xl, 64..127 = xr
__device__ float  g_h[NN * C];
__device__ float  g_h2[NN * C];
__device__ float  g_P12[NN * 512];    // cols 0..255 = P1, 256..511 = P2
__device__ float  g_Wp1[DIN * 128];
__device__ float  g_Wp2[C * 128];
__device__ float  g_WpC[C * 512];
__device__ float  g_Wep[DE * 128];    // [We1 | We2]
__device__ float  g_bp1[128];
__device__ float  g_bp2[128];

__device__ __forceinline__ float lrelu(float x) { return x > 0.f ? x : NEG * x; }
__device__ __forceinline__ float eluf(float x)  { return x > 0.f ? x : __expf(x) - 1.f; }

typedef unsigned long long ull;
__device__ __forceinline__ ull pack2(float lo, float hi) {
    ull r;
    asm("mov.b64 %0, {%1, %2};" : "=l"(r) : "f"(lo), "f"(hi));
    return r;
}
__device__ __forceinline__ void unpack2(ull v, float& lo, float& hi) {
    asm("mov.b64 {%0, %1}, %2;" : "=f"(lo), "=f"(hi) : "l"(v));
}
__device__ __forceinline__ ull ffma2(ull a, ull b, ull c) {
    ull d;
    asm("fma.rn.f32x2 %0, %1, %2, %3;" : "=l"(d) : "l"(a), "l"(b), "l"(c));
    return d;
}
__device__ __forceinline__ ull add2(ull a, ull b) {
    ull d;
    asm("add.rn.f32x2 %0, %1, %2;" : "=l"(d) : "l"(a), "l"(b));
    return d;
}
__device__ __forceinline__ ull mul2(ull a, ull b) {
    ull d;
    asm("mul.rn.f32x2 %0, %1, %2;" : "=l"(d) : "l"(a), "l"(b));
    return d;
}

// ---------------- launch 1: pack weights + degree histogram ------------------
__global__ void prep_kernel(const float* __restrict__ W1l, const float* __restrict__ W1r,
                            const float* __restrict__ b1l, const float* __restrict__ b1r,
                            const float* __restrict__ W2l, const float* __restrict__ W2r,
                            const float* __restrict__ b2l, const float* __restrict__ b2r,
                            const float* __restrict__ We1, const float* __restrict__ We2,
                            const float* __restrict__ Cw1,
                            const int* __restrict__ ei) {
    int i = blockIdx.x * blockDim.x + threadIdx.x;
    if (i < EE) atomicAdd(&g_cnt[ei[EE + i]], 1);   // g_cnt zeroed by prior scan_final
    if (i < DIN * 128) {
        int k = i >> 7, c = i & 127;
        g_Wp1[i] = (c < 64) ? W1l[k * 64 + c] : W1r[k * 64 + c - 64];
    }
    if (i < DE * 128) {
        int k = i >> 7, c = i & 127;
        g_Wep[i] = (c < 64) ? We1[k * 64 + c] : We2[k * 64 + c - 64];
    }
    int j = i - DIN * 128;
    if (j >= 0 && j < C * 128) {
        int k = j >> 7, c = j & 127;
        g_Wp2[j] = (c < 64) ? W2l[k * 64 + c] : W2r[k * 64 + c - 64];
    }
    int l = i - DIN * 128 - C * 128;
    if (l >= 0 && l < C * 512) {
        int k = l >> 9, c = l & 511;
        g_WpC[l] = (c < 256) ? Cw1[k * 256 + c] : Cw1[(64 + k) * 256 + c - 256];
    }
    if (i < 128) {
        g_bp1[i] = (i < 64) ? b1l[i] : b1r[i - 64];
        g_bp2[i] = (i < 64) ? b2l[i] : b2r[i - 64];
    }
}

// ---------------- parallel 3-kernel scan -------------------------------------
__global__ void scan_blocksum_kernel() {
    __shared__ int sw[32];
    int i = blockIdx.x * 1024 + threadIdx.x;
    int v = (i < NN) ? g_cnt[i] : 0;
    #pragma unroll
    for (int o = 16; o; o >>= 1) v += __shfl_xor_sync(0xffffffffu, v, o);
    if ((threadIdx.x & 31) == 0) sw[threadIdx.x >> 5] = v;
    __syncthreads();
    if (threadIdx.x < 32) {
        int s = sw[threadIdx.x];
        #pragma unroll
        for (int o = 16; o; o >>= 1) s += __shfl_xor_sync(0xffffffffu, s, o);
        if (threadIdx.x == 0) g_bsum[blockIdx.x] = s;
    }
}

__global__ void scan_offsets_kernel(int nblocks) {
    __shared__ int s[64];
    int t = threadIdx.x;
    s[t] = (t < nblocks) ? g_bsum[t] : 0;
    __syncthreads();
    #pragma unroll
    for (int off = 1; off < 64; off <<= 1) {
        int v = (t >= off) ? s[t - off] : 0;
        __syncthreads();
        s[t] += v;
        __syncthreads();
    }
    if (t < nblocks) g_boff[t] = s[t] - g_bsum[t];   // exclusive
}

// per-block exclusive scan + global offset; re-zeroes g_cnt for the next run
__global__ void scan_final_kernel() {
    __shared__ int s[1024];
    int t = threadIdx.x;
    int i = blockIdx.x * 1024 + t;
    int v = 0;
    if (i < NN) { v = g_cnt[i]; g_cnt[i] = 0; }
    s[t] = v;
    __syncthreads();
    #pragma unroll
    for (int off = 1; off < 1024; off <<= 1) {
        int u = (t >= off) ? s[t - off] : 0;
        __syncthreads();
        s[t] += u;
        __syncthreads();
    }
    int excl = g_boff[blockIdx.x] + s[t] - v;
    if (i < NN) {
        g_rowptr[i] = excl;
        g_cursor[i] = excl;
        if (i == NN - 1) g_rowptr[NN] = excl + v;
    }
}

// ---------------- tf32 WMMA GEMM body ----------------------------------------
constexpr int LDA = 40;
constexpr int LDB = 72;
constexpr int LDO = 72;
constexpr int LDA2 = 24;   // ewe A tile: 16 + 8 pad

constexpr int SM_GEMM = 64 * LDA + 32 * LDB;                      // 4864
constexpr int SM_EWE2 = 64 * LDA2 + 2 * 16 * LDB + 64 * LDO;      // 8448

__device__ void gemm_body(float* sm,
                          const float* __restrict__ X,
                          const float* __restrict__ W,
                          const float* __restrict__ bias,
                          float* __restrict__ Cmat,
                          int n, int K, int Cout,
                          int rowTile, int colTile) {
    float* As = sm;
    float* Bs = sm + 64 * LDA;
    float* sOut = sm;

    int tid = threadIdx.x;
    int warpId = tid >> 5;
    int rowBase = rowTile * 64;
    int colB    = colTile * 64;
    int warpRow = (warpId & 3) * 16;
    int warpCol = (warpId >> 2) * 32;

    wmma::fragment<wmma::accumulator, 16, 16, 8, float> acc0, acc1;
    wmma::fill_fragment(acc0, 0.f);
    wmma::fill_fragment(acc1, 0.f);

    for (int kt = 0; kt < K; kt += 32) {
        #pragma unroll
        for (int f = tid; f < 512; f += 256) {
            int row = f >> 3, kq = f & 7;
            float4 v = make_float4(0.f, 0.f, 0.f, 0.f);
            if (rowBase + row < n)
                v = *(const float4*)&X[(size_t)(rowBase + row) * K + kt + kq * 4];
            float* d = &As[row * LDA + kq * 4];
            d[0] = wmma::__float_to_tf32(v.x);
            d[1] = wmma::__float_to_tf32(v.y);
            d[2] = wmma::__float_to_tf32(v.z);
            d[3] = wmma::__float_to_tf32(v.w);
        }
        #pragma unroll
        for (int f = tid; f < 512; f += 256) {
            int row = f >> 4, cq = f & 15;
            float4 v = *(const float4*)&W[(size_t)(kt + row) * Cout + colB + cq * 4];
            float* d = &Bs[row * LDB + cq * 4];
            d[0] = wmma::__float_to_tf32(v.x);
            d[1] = wmma::__float_to_tf32(v.y);
            d[2] = wmma::__float_to_tf32(v.z);
            d[3] = wmma::__float_to_tf32(v.w);
        }
        __syncthreads();
        #pragma unroll
        for (int kk = 0; kk < 32; kk += 8) {
            wmma::fragment<wmma::matrix_a, 16, 16, 8, wmma::precision::tf32, wmma::row_major> a;
            wmma::fragment<wmma::matrix_b, 16, 16, 8, wmma::precision::tf32, wmma::row_major> b0, b1;
            wmma::load_matrix_sync(a, &As[warpRow * LDA + kk], LDA);
            wmma::load_matrix_sync(b0, &Bs[kk * LDB + warpCol], LDB);
            wmma::load_matrix_sync(b1, &Bs[kk * LDB + warpCol + 16], LDB);
            wmma::mma_sync(acc0, a, b0, acc0);
            wmma::mma_sync(acc1, a, b1, acc1);
        }
        __syncthreads();
    }

    wmma::store_matrix_sync(&sOut[warpRow * LDO + warpCol],      acc0, LDO, wmma::mem_row_major);
    wmma::store_matrix_sync(&sOut[warpRow * LDO + warpCol + 16], acc1, LDO, wmma::mem_row_major);
    __syncthreads();
    #pragma unroll
    for (int f = tid; f < 1024; f += 256) {
        int row = f >> 4, cq = f & 15;
        if (rowBase + row < n) {
            float4 v = *(float4*)&sOut[row * LDO + cq * 4];
            if (bias) {
                float4 b = *(const float4*)&bias[colB + cq * 4];
                v.x += b.x; v.y += b.y; v.z += b.z; v.w += b.w;
            }
            *(float4*)&Cmat[(size_t)(rowBase + row) * Cout + colB + cq * 4] = v;
        }
    }
}

__global__ void gemm_tf32_kernel(const float* __restrict__ X,
                                 const float* __restrict__ W,
                                 const float* __restrict__ bias,
                                 float* __restrict__ Cmat,
                                 int n, int K, int Cout) {
    __shared__ float sm[SM_GEMM];
    gemm_body(sm, X, W, bias, Cmat, n, K, Cout, blockIdx.x, blockIdx.y);
}

// ---------------- CSR scatter + layer-1 GEMM (fused) -------------------------
__global__ void scatter_gemm_kernel(const int* __restrict__ ei,
                                    const float* __restrict__ X) {
    __shared__ float sm[SM_GEMM];
    if (blockIdx.x < SCAT_BLOCKS) {
        int e = blockIdx.x * blockDim.x + threadIdx.x;
        if (e >= EE) return;
        int dst = ei[EE + e];
        int pos = atomicAdd(&g_cursor[dst], 1);
        g_csr_se[pos] = make_int2(ei[e], e);
    } else {
        int gb = blockIdx.x - SCAT_BLOCKS;
        int colTile = gb / ROW_BLOCKS;
        int rowTile = gb - colTile * ROW_BLOCKS;
        gemm_body(sm, X, g_Wp1, g_bp1, g_xlr, NN, DIN, 128, rowTile, colTile);
    }
}

// ---------------- ewe GEMM standalone (wmma, fp16 out, both layers) ----------
// (R13 version, measured 80.9 us)
__global__ __launch_bounds__(256)
void ewe_kernel(const float* __restrict__ eattr) {
    __shared__ float sm[SM_EWE2];
    float* As   = sm;                               // 64 * LDA2
    float* Bs   = sm + 64 * LDA2;                   // 2 * 16 * LDB
    float* sOut = sm + 64 * LDA2 + 2 * 16 * LDB;    // 64 * LDO

    int tid = threadIdx.x;
    int lane = tid & 31;
    int eBase = blockIdx.x * 64;

    {   // A: 64 edges x 16 attrs
        int row = tid >> 2, kq = tid & 3;
        float4 v = *(const float4*)&eattr[(size_t)(eBase + row) * 16 + kq * 4];
        float* d = &As[row * LDA2 + kq * 4];
        d[0] = wmma::__float_to_tf32(v.x);
        d[1] = wmma::__float_to_tf32(v.y);
        d[2] = wmma::__float_to_tf32(v.z);
        d[3] = wmma::__float_to_tf32(v.w);
    }
    {   // both B halves: 2 x 16 x 64 = 512 float4 slots
        #pragma unroll
        for (int f = tid; f < 512; f += 256) {
            int half = f >> 8;
            int r = (f >> 4) & 15;
            int cq = f & 15;
            float4 v = *(const float4*)&g_Wep[r * 128 + half * 64 + cq * 4];
            float* d = &Bs[half * 16 * LDB + r * LDB + cq * 4];
            d[0] = wmma::__float_to_tf32(v.x);
            d[1] = wmma::__float_to_tf32(v.y);
            d[2] = wmma::__float_to_tf32(v.z);
            d[3] = wmma::__float_to_tf32(v.w);
        }
    }
    __syncthreads();

    int warpId = tid >> 5;
    int warpRow = (warpId & 3) * 16;
    int warpCol = (warpId >> 2) * 32;

    #pragma unroll
    for (int half = 0; half < 2; half++) {
        const float* Bh = Bs + half * 16 * LDB;
        wmma::fragment<wmma::accumulator, 16, 16, 8, float> acc0, acc1;
        wmma::fill_fragment(acc0, 0.f);
        wmma::fill_fragment(acc1, 0.f);
        #pragma unroll
        for (int kk = 0; kk < 16; kk += 8) {
            wmma::fragment<wmma::matrix_a, 16, 16, 8, wmma::precision::tf32, wmma::row_major> a;
            wmma::fragment<wmma::matrix_b, 16, 16, 8, wmma::precision::tf32, wmma::row_major> b0, b1;
            wmma::load_matrix_sync(a, &As[warpRow * LDA2 + kk], LDA2);
            wmma::load_matrix_sync(b0, &Bh[kk * LDB + warpCol], LDB);
            wmma::load_matrix_sync(b1, &Bh[kk * LDB + warpCol + 16], LDB);
            wmma::mma_sync(acc0, a, b0, acc0);
            wmma::mma_sync(acc1, a, b1, acc1);
        }
        wmma::store_matrix_sync(&sOut[warpRow * LDO + warpCol],      acc0, LDO, wmma::mem_row_major);
        wmma::store_matrix_sync(&sOut[warpRow * LDO + warpCol + 16], acc1, LDO, wmma::mem_row_major);
        __syncwarp();
        __half* out = half ? g_ewe2 : g_ewe1;
        #pragma unroll
        for (int q = 0; q < 4; q++) {
            int slot = q * 32 + lane;        // 128 slots = 16 rows x 8 col-groups
            int row = warpRow + (slot >> 3);
            int col = warpCol + (slot & 7) * 4;
            float4 v = *(float4*)&sOut[row * LDO + col];
            __half2 h0 = __float22half2_rn(make_float2(v.x, v.y));
            __half2 h1 = __float22half2_rn(make_float2(v.z, v.w));
            uint2 pkd = make_uint2(*(unsigned*)&h0, *(unsigned*)&h1);
            *(uint2*)&out[(size_t)(eBase + row) * 64 + col] = pkd;
        }
        __syncwarp();
    }
}

// ---------------- fused GAT layer: warp/node, fp16 ewe by eid, 2-edge unroll -
__global__ __launch_bounds__(256)
void gat_layer_kernel(const __half* __restrict__ ewe,
                      const float* __restrict__ att,
                      const float* __restrict__ bias,
                      float* __restrict__ outbuf,
                      int doElu) {
    int lane = threadIdx.x & 31;
    int node = (blockIdx.x * blockDim.x + threadIdx.x) >> 5;
    if (node >= NN) return;

    float2 a2 = ((const float2*)att)[lane];
    float2 b2 = ((const float2*)bias)[lane];
    const float2* xlr2 = (const float2*)g_xlr;
    const __half2* ewe2 = (const __half2*)ewe;

    int start = g_rowptr[node], end = g_rowptr[node + 1];
    float2 rf  = xlr2[node * 64 + 32 + lane];
    float2 vSf = xlr2[node * 64 + lane];
    ull r2  = pack2(rf.x, rf.y);
    ull vS2 = pack2(vSf.x, vSf.y);

    float amax = -INFINITY, den = 0.f;
    ull acc = 0, wsum = 0;

    ull vA = 0, wA = 0, vB = 0, wB = 0;
    if (start < end) {
        int2 se = g_csr_se[start];
        float2 t = xlr2[se.x * 64 + lane];            vA = pack2(t.x, t.y);
        float2 u = __half22float2(ewe2[(size_t)se.y * 32 + lane]); wA = pack2(u.x, u.y);
    }
    if (start + 1 < end) {
        int2 se = g_csr_se[start + 1];
        float2 t = xlr2[se.x * 64 + lane];            vB = pack2(t.x, t.y);
        float2 u = __half22float2(ewe2[(size_t)se.y * 32 + lane]); wB = pack2(u.x, u.y);
    }

    int p = start;
    for (; p + 1 < end; p += 2) {
        ull v0 = vA, w0 = wA, v1 = vB, w1 = wB;
        if (p + 2 < end) {
            int2 se = g_csr_se[p + 2];
            float2 t = xlr2[se.x * 64 + lane];            vA = pack2(t.x, t.y);
            float2 u = __half22float2(ewe2[(size_t)se.y * 32 + lane]); wA = pack2(u.x, u.y);
        }
        if (p + 3 < end) {
            int2 se = g_csr_se[p + 3];
            float2 t = xlr2[se.x * 64 + lane];            vB = pack2(t.x, t.y);
            float2 u = __half22float2(ewe2[(size_t)se.y * 32 + lane]); wB = pack2(u.x, u.y);
        }
        wsum = add2(wsum, add2(w0, w1));
        ull m0 = add2(add2(v0, r2), w0);
        ull m1 = add2(add2(v1, r2), w1);
        float m0x, m0y, m1x, m1y;
        unpack2(m0, m0x, m0y);
        unpack2(m1, m1x, m1y);
        float pk0 = lrelu(m0x) * a2.x + lrelu(m0y) * a2.y;
        float pk1 = lrelu(m1x) * a2.x + lrelu(m1y) * a2.y;
        #pragma unroll
        for (int o = 16; o; o >>= 1) {
            pk0 += __shfl_xor_sync(0xffffffffu, pk0, o);
            pk1 += __shfl_xor_sync(0xffffffffu, pk1, o);
        }
        float pm = fmaxf(pk0, pk1);
        if (pm > amax) {
            float f = __expf(amax - pm);
            den *= f;
            acc = mul2(acc, pack2(f, f));
            amax = pm;
        }
        float e0 = __expf(pk0 - amax), e1 = __expf(pk1 - amax);
        den += e0 + e1;
        acc = ffma2(pack2(e0, e0), v0, acc);
        acc = ffma2(pack2(e1, e1), v1, acc);
    }
    if (p < end) {   // odd tail
        wsum = add2(wsum, wA);
        ull m0 = add2(add2(vA, r2), wA);
        float m0x, m0y;
        unpack2(m0, m0x, m0y);
        float pk0 = lrelu(m0x) * a2.x + lrelu(m0y) * a2.y;
        #pragma unroll
        for (int o = 16; o; o >>= 1) pk0 += __shfl_xor_sync(0xffffffffu, pk0, o);
        if (pk0 > amax) {
            float f = __expf(amax - pk0);
            den *= f;
            acc = mul2(acc, pack2(f, f));
            amax = pk0;
        }
        float e0 = __expf(pk0 - amax);
        den += e0;
        acc = ffma2(pack2(e0, e0), vA, acc);
    }

    // self loop: ewe_self = mean(ewe) over incoming edges (linearity of @We)
    float invdeg = 1.f / fmaxf((float)(end - start), 1.f);
    ull mS = add2(add2(vS2, r2), mul2(wsum, pack2(invdeg, invdeg)));
    float msx, msy;
    unpack2(mS, msx, msy);
    float pS = lrelu(msx) * a2.x + lrelu(msy) * a2.y;
    #pragma unroll
    for (int o = 16; o; o >>= 1) pS += __shfl_xor_sync(0xffffffffu, pS, o);
    if (pS > amax) {
        float f = __expf(amax - pS);
        den *= f;
        acc = mul2(acc, pack2(f, f));
        amax = pS;
    }
    float eS = __expf(pS - amax);
    den += eS;
    acc = ffma2(pack2(eS, eS), vS2, acc);

    float inv = 1.f / den;
    float accx, accy;
    unpack2(acc, accx, accy);
    float ox = accx * inv + b2.x;
    float oy = accy * inv + b2.y;
    if (doElu) { ox = eluf(ox); oy = eluf(oy); }
    ((float2*)outbuf)[node * 32 + lane] = make_float2(ox, oy);
}

// ---------------- edge classifier: warp per edge PAIR, fp16 weights ----------
__global__ __launch_bounds__(128)
void classifier_kernel(const float* __restrict__ eattr,
                       const int* __restrict__ ei,
                       const float* __restrict__ Cw1c,   // [16][256]
                       const float* __restrict__ Cb1,
                       const float* __restrict__ Cw2,
                       const float* __restrict__ Cb2,
                       float* __restrict__ out) {
    int lane = threadIdx.x & 31;
    int c0 = 4 * lane;
    __half2 wh[DE][4];
    #pragma unroll
    for (int k = 0; k < DE; k++) {
        float4 A = *(const float4*)&Cw1c[k * HID + c0];
        float4 B = *(const float4*)&Cw1c[k * HID + 128 + c0];
        wh[k][0] = __floats2half2_rn(A.x, A.y);
        wh[k][1] = __floats2half2_rn(A.z, A.w);
        wh[k][2] = __floats2half2_rn(B.x, B.y);
        wh[k][3] = __floats2half2_rn(B.z, B.w);
    }
    float4 b0 = *(const float4*)&Cb1[c0];
    float4 b1 = *(const float4*)&Cb1[128 + c0];
    float4 c20 = *(const float4*)&Cw2[c0];
    float4 c21 = *(const float4*)&Cw2[128 + c0];
    float cb2 = Cb2[0];

    const float4* P  = (const float4*)g_P12;
    const float4* EA = (const float4*)eattr;
    int pairGid = (blockIdx.x * blockDim.x + threadIdx.x) >> 5;
    int pairsTotal = (gridDim.x * blockDim.x) >> 5;
    const int NPAIR = EE / 2;

    for (int pr = pairGid; pr < NPAIR; pr += pairsTotal) {
        int e0 = 2 * pr, e1 = 2 * pr + 1;
        int src0 = ei[e0], dst0 = ei[EE + e0];
        int src1 = ei[e1], dst1 = ei[EE + e1];
        float4 p1a0 = P[(size_t)src0 * 128 + lane];
        float4 p1b0 = P[(size_t)src0 * 128 + 32 + lane];
        float4 p2a0 = P[(size_t)dst0 * 128 + 64 + lane];
        float4 p2b0 = P[(size_t)dst0 * 128 + 96 + lane];
        float4 p1a1 = P[(size_t)src1 * 128 + lane];
        float4 p1b1 = P[(size_t)src1 * 128 + 32 + lane];
        float4 p2a1 = P[(size_t)dst1 * 128 + 64 + lane];
        float4 p2b1 = P[(size_t)dst1 * 128 + 96 + lane];
        __half2 x0 = __float2half2_rn(0.f), x1 = x0, x2 = x0, x3 = x0;
        __half2 y0 = x0, y1 = x0, y2 = x0, y3 = x0;
        #pragma unroll
        for (int kq = 0; kq < 4; kq++) {
            float4 ea0 = EA[(size_t)e0 * 4 + kq];
            float4 ea1 = EA[(size_t)e1 * 4 + kq];
            const float* e0p = (const float*)&ea0;
            const float* e1p = (const float*)&ea1;
            #pragma unroll
            for (int j = 0; j < 4; j++) {
                int k = kq * 4 + j;
                __half2 s0 = __float2half2_rn(e0p[j]);
                __half2 s1 = __float2half2_rn(e1p[j]);
                x0 = __hfma2(s0, wh[k][0], x0);
                x1 = __hfma2(s0, wh[k][1], x1);
                x2 = __hfma2(s0, wh[k][2], x2);
                x3 = __hfma2(s0, wh[k][3], x3);
                y0 = __hfma2(s1, wh[k][0], y0);
                y1 = __hfma2(s1, wh[k][1], y1);
                y2 = __hfma2(s1, wh[k][2], y2);
                y3 = __hfma2(s1, wh[k][3], y3);
            }
        }
        float2 f0 = __half22float2(x0), f1 = __half22float2(x1);
        float2 f2 = __half22float2(x2), f3 = __half22float2(x3);
        float2 g0 = __half22float2(y0), g1 = __half22float2(y1);
        float2 g2 = __half22float2(y2), g3 = __half22float2(y3);
        float acc0 =
              eluf(f0.x + p1a0.x + p2a0.x + b0.x) * c20.x
            + eluf(f0.y + p1a0.y + p2a0.y + b0.y) * c20.y
            + eluf(f1.x + p1a0.z + p2a0.z + b0.z) * c20.z
            + eluf(f1.y + p1a0.w + p2a0.w + b0.w) * c20.w
            + eluf(f2.x + p1b0.x + p2b0.x + b1.x) * c21.x
            + eluf(f2.y + p1b0.y + p2b0.y + b1.y) * c21.y
            + eluf(f3.x + p1b0.z + p2b0.z + b1.z) * c21.z
            + eluf(f3.y + p1b0.w + p2b0.w + b1.w) * c21.w;
        float acc1 =
              eluf(g0.x + p1a1.x + p2a1.x + b0.x) * c20.x
            + eluf(g0.y + p1a1.y + p2a1.y + b0.y) * c20.y
            + eluf(g1.x + p1a1.z + p2a1.z + b0.z) * c20.z
            + eluf(g1.y + p1a1.w + p2a1.w + b0.w) * c20.w
            + eluf(g2.x + p1b1.x + p2b1.x + b1.x) * c21.x
            + eluf(g2.y + p1b1.y + p2b1.y + b1.y) * c21.y
            + eluf(g3.x + p1b1.z + p2b1.z + b1.z) * c21.z
            + eluf(g3.y + p1b1.w + p2b1.w + b1.w) * c21.w;
        #pragma unroll
        for (int o = 16; o; o >>= 1) {
            acc0 += __shfl_xor_sync(0xffffffffu, acc0, o);
            acc1 += __shfl_xor_sync(0xffffffffu, acc1, o);
        }
        if (lane == 0) {
            out[e0] = acc0 + cb2;
            out[e1] = acc1 + cb2;
        }
    }
}

// ---------------- host orchestration ----------------------------------------
static inline int ceil_div(int a, int b) { return (a + b - 1) / b; }

extern "C" void kernel_launch(void* const* d_in, const int* in_sizes, int n_in,
                              void* d_out, int out_size) {
    const float* x     = (const float*)d_in[0];
    const float* eattr = (const float*)d_in[1];
    const float* W1l   = (const float*)d_in[2];
    const float* b1l   = (const float*)d_in[3];
    const float* W1r   = (const float*)d_in[4];
    const float* b1r   = (const float*)d_in[5];
    const float* We1   = (const float*)d_in[6];
    const float* att1  = (const float*)d_in[7];
    const float* bias1 = (const float*)d_in[8];
    const float* W2l   = (const float*)d_in[9];
    const float* b2l   = (const float*)d_in[10];
    const float* W2r   = (const float*)d_in[11];
    const float* b2r   = (const float*)d_in[12];
    const float* We2   = (const float*)d_in[13];
    const float* att2  = (const float*)d_in[14];
    const float* bias2 = (const float*)d_in[15];
    // d_in[16..19] (Aw1/Ab1/Aw2/Ab2): softmax over a single column == 1 -> unused
    const float* Cw1   = (const float*)d_in[20];
    const float* Cb1   = (const float*)d_in[21];
    const float* Cw2   = (const float*)d_in[22];
    const float* Cb2   = (const float*)d_in[23];
    const int*   ei    = (const int*)  d_in[24];
    float* out = (float*)d_out;

    float *d_h, *d_h2, *d_P12, *d_Wp2, *d_WpC, *d_bp2, *d_xlr;
    __half *d_ewe1, *d_ewe2;
    cudaGetSymbolAddress((void**)&d_h,    g_h);
    cudaGetSymbolAddress((void**)&d_h2,   g_h2);
    cudaGetSymbolAddress((void**)&d_P12,  g_P12);
    cudaGetSymbolAddress((void**)&d_Wp2,  g_Wp2);
    cudaGetSymbolAddress((void**)&d_WpC,  g_WpC);
    cudaGetSymbolAddress((void**)&d_bp2,  g_bp2);
    cudaGetSymbolAddress((void**)&d_xlr,  g_xlr);
    cudaGetSymbolAddress((void**)&d_ewe1, g_ewe1);
    cudaGetSymbolAddress((void**)&d_ewe2, g_ewe2);

    const int TB = 256;
    int gatBlocks = ceil_div(NN * 32, TB);

    // 1: pack weights + histogram
    prep_kernel<<<ceil_div(EE, TB), TB>>>(W1l, W1r, b1l, b1r, W2l, W2r, b2l, b2r,
                                          We1, We2, Cw1, ei);
    // 2-3: parallel scan (block sums + offsets)
    scan_blocksum_kernel<<<SCAN_BLOCKS, 1024>>>();
    scan_offsets_kernel<<<1, 64>>>(SCAN_BLOCKS);
    // 4: ewe GEMM (independent of scan)  (ncu capture slot)
    ewe_kernel<<<EWE_BLOCKS, 256>>>(eattr);
    // 5: scan finalize (+ re-zero g_cnt)
    scan_final_kernel<<<SCAN_BLOCKS, 1024>>>();
    // 6: CSR scatter + layer-1 GEMM fused
    scatter_gemm_kernel<<<SCAT_BLOCKS + 2 * ROW_BLOCKS, 256>>>(ei, x);
    // 7: GAT layer 1
    gat_layer_kernel<<<gatBlocks, TB>>>(d_ewe1, att1, bias1, d_h, 1);
    // 8-9: layer 2
    gemm_tf32_kernel<<<dim3(ROW_BLOCKS, 2), 256>>>(d_h, d_Wp2, d_bp2, d_xlr, NN, C, 128);
    gat_layer_kernel<<<gatBlocks, TB>>>(d_ewe2, att2, bias2, d_h2, 0);
    // 10-11: classifier
    gemm_tf32_kernel<<<dim3(ROW_BLOCKS, 8), 256>>>(d_h2, d_WpC, nullptr, d_P12, NN, C, 512);
    classifier_kernel<<<2368, 128>>>(eattr, ei, Cw1 + 2 * C * HID, Cb1, Cw2, Cb2, out);
}

// round 16
// speedup vs baseline: 1.1757x; 1.0188x over previous
#include <cuda_runtime.h>
#include <cuda_fp16.h>
#include <mma.h>
#include <math.h>

using namespace nvcuda;

constexpr int NN   = 50000;
constexpr int EE   = 800000;
constexpr int DIN  = 128;
constexpr int DE   = 16;
constexpr int C    = 64;
constexpr int HID  = 256;
constexpr float NEG = 0.2f;

constexpr int SCAT_BLOCKS = (EE + 255) / 256;        // 3125
constexpr int ROW_BLOCKS  = (NN + 63) / 64;          // 782
constexpr int EWE_BLOCKS  = EE / 64;                 // 12500 (exact)
constexpr int SCAN_BLOCKS = (NN + 1023) / 1024;      // 49

// ---------------- device scratch --------------------------------------------
__device__ int    g_cnt[NN];          // zero at load; re-zeroed by scan_final
__device__ int    g_rowptr[NN + 1];
__device__ int    g_cursor[NN];
__device__ int    g_bsum[64];
__device__ int    g_boff[64];
__device__ int2   g_csr_se[EE];       // (src, eid) per CSR slot
__device__ __half g_ewe1[(size_t)EE * 64];   // layer-1 e@We, fp16
__device__ __half g_ewe2[(size_t)EE * 64];   // layer-2 e@We, fp16
__device__ float  g_xlr[NN * 128];    // cols 0..63 = xl, 64..127 = xr
__device__ float  g_h[NN * C];
__device__ float  g_h2[NN * C];
__device__ float  g_P12[NN * 512];    // cols 0..255 = P1, 256..511 = P2
__device__ float  g_Wp1[DIN * 128];
__device__ float  g_Wp2[C * 128];
__device__ float  g_WpC[C * 512];
__device__ float  g_Wep[DE * 128];    // [We1 | We2]
__device__ float  g_bp1[128];
__device__ float  g_bp2[128];

__device__ __forceinline__ float lrelu(float x) { return x > 0.f ? x : NEG * x; }
__device__ __forceinline__ float eluf(float x)  { return x > 0.f ? x : __expf(x) - 1.f; }

typedef unsigned long long ull;
__device__ __forceinline__ ull pack2(float lo, float hi) {
    ull r;
    asm("mov.b64 %0, {%1, %2};" : "=l"(r) : "f"(lo), "f"(hi));
    return r;
}
__device__ __forceinline__ void unpack2(ull v, float& lo, float& hi) {
    asm("mov.b64 {%0, %1}, %2;" : "=f"(lo), "=f"(hi) : "l"(v));
}
__device__ __forceinline__ ull ffma2(ull a, ull b, ull c) {
    ull d;
    asm("fma.rn.f32x2 %0, %1, %2, %3;" : "=l"(d) : "l"(a), "l"(b), "l"(c));
    return d;
}
__device__ __forceinline__ ull add2(ull a, ull b) {
    ull d;
    asm("add.rn.f32x2 %0, %1, %2;" : "=l"(d) : "l"(a), "l"(b));
    return d;
}
__device__ __forceinline__ ull mul2(ull a, ull b) {
    ull d;
    asm("mul.rn.f32x2 %0, %1, %2;" : "=l"(d) : "l"(a), "l"(b));
    return d;
}

// ---------------- launch 1: pack weights + degree histogram ------------------
__global__ void prep_kernel(const float* __restrict__ W1l, const float* __restrict__ W1r,
                            const float* __restrict__ b1l, const float* __restrict__ b1r,
                            const float* __restrict__ W2l, const float* __restrict__ W2r,
                            const float* __restrict__ b2l, const float* __restrict__ b2r,
                            const float* __restrict__ We1, const float* __restrict__ We2,
                            const float* __restrict__ Cw1,
                            const int* __restrict__ ei) {
    int i = blockIdx.x * blockDim.x + threadIdx.x;
    if (i < EE) atomicAdd(&g_cnt[ei[EE + i]], 1);
    if (i < DIN * 128) {
        int k = i >> 7, c = i & 127;
        g_Wp1[i] = (c < 64) ? W1l[k * 64 + c] : W1r[k * 64 + c - 64];
    }
    if (i < DE * 128) {
        int k = i >> 7, c = i & 127;
        g_Wep[i] = (c < 64) ? We1[k * 64 + c] : We2[k * 64 + c - 64];
    }
    int j = i - DIN * 128;
    if (j >= 0 && j < C * 128) {
        int k = j >> 7, c = j & 127;
        g_Wp2[j] = (c < 64) ? W2l[k * 64 + c] : W2r[k * 64 + c - 64];
    }
    int l = i - DIN * 128 - C * 128;
    if (l >= 0 && l < C * 512) {
        int k = l >> 9, c = l & 511;
        g_WpC[l] = (c < 256) ? Cw1[k * 256 + c] : Cw1[(64 + k) * 256 + c - 256];
    }
    if (i < 128) {
        g_bp1[i] = (i < 64) ? b1l[i] : b1r[i - 64];
        g_bp2[i] = (i < 64) ? b2l[i] : b2r[i - 64];
    }
}

// ---------------- parallel 3-kernel scan -------------------------------------
__global__ void scan_blocksum_kernel() {
    __shared__ int sw[32];
    int i = blockIdx.x * 1024 + threadIdx.x;
    int v = (i < NN) ? g_cnt[i] : 0;
    #pragma unroll
    for (int o = 16; o; o >>= 1) v += __shfl_xor_sync(0xffffffffu, v, o);
    if ((threadIdx.x & 31) == 0) sw[threadIdx.x >> 5] = v;
    __syncthreads();
    if (threadIdx.x < 32) {
        int s = sw[threadIdx.x];
        #pragma unroll
        for (int o = 16; o; o >>= 1) s += __shfl_xor_sync(0xffffffffu, s, o);
        if (threadIdx.x == 0) g_bsum[blockIdx.x] = s;
    }
}

__global__ void scan_offsets_kernel(int nblocks) {
    __shared__ int s[64];
    int t = threadIdx.x;
    s[t] = (t < nblocks) ? g_bsum[t] : 0;
    __syncthreads();
    #pragma unroll
    for (int off = 1; off < 64; off <<= 1) {
        int v = (t >= off) ? s[t - off] : 0;
        __syncthreads();
        s[t] += v;
        __syncthreads();
    }
    if (t < nblocks) g_boff[t] = s[t] - g_bsum[t];
}

__global__ void scan_final_kernel() {
    __shared__ int s[1024];
    int t = threadIdx.x;
    int i = blockIdx.x * 1024 + t;
    int v = 0;
    if (i < NN) { v = g_cnt[i]; g_cnt[i] = 0; }
    s[t] = v;
    __syncthreads();
    #pragma unroll
    for (int off = 1; off < 1024; off <<= 1) {
        int u = (t >= off) ? s[t - off] : 0;
        __syncthreads();
        s[t] += u;
        __syncthreads();
    }
    int excl = g_boff[blockIdx.x] + s[t] - v;
    if (i < NN) {
        g_rowptr[i] = excl;
        g_cursor[i] = excl;
        if (i == NN - 1) g_rowptr[NN] = excl + v;
    }
}

// ---------------- tf32 WMMA GEMM body ----------------------------------------
constexpr int LDA = 40;
constexpr int LDB = 72;
constexpr int LDO = 72;
constexpr int LDA2 = 24;

constexpr int SM_GEMM = 64 * LDA + 32 * LDB;                      // 4864
constexpr int SM_EWE2 = 64 * LDA2 + 2 * 16 * LDB + 64 * LDO;      // 8448

__device__ void gemm_body(float* sm,
                          const float* __restrict__ X,
                          const float* __restrict__ W,
                          const float* __restrict__ bias,
                          float* __restrict__ Cmat,
                          int n, int K, int Cout,
                          int rowTile, int colTile) {
    float* As = sm;
    float* Bs = sm + 64 * LDA;
    float* sOut = sm;

    int tid = threadIdx.x;
    int warpId = tid >> 5;
    int rowBase = rowTile * 64;
    int colB    = colTile * 64;
    int warpRow = (warpId & 3) * 16;
    int warpCol = (warpId >> 2) * 32;

    wmma::fragment<wmma::accumulator, 16, 16, 8, float> acc0, acc1;
    wmma::fill_fragment(acc0, 0.f);
    wmma::fill_fragment(acc1, 0.f);

    for (int kt = 0; kt < K; kt += 32) {
        #pragma unroll
        for (int f = tid; f < 512; f += 256) {
            int row = f >> 3, kq = f & 7;
            float4 v = make_float4(0.f, 0.f, 0.f, 0.f);
            if (rowBase + row < n)
                v = *(const float4*)&X[(size_t)(rowBase + row) * K + kt + kq * 4];
            float* d = &As[row * LDA + kq * 4];
            d[0] = wmma::__float_to_tf32(v.x);
            d[1] = wmma::__float_to_tf32(v.y);
            d[2] = wmma::__float_to_tf32(v.z);
            d[3] = wmma::__float_to_tf32(v.w);
        }
        #pragma unroll
        for (int f = tid; f < 512; f += 256) {
            int row = f >> 4, cq = f & 15;
            float4 v = *(const float4*)&W[(size_t)(kt + row) * Cout + colB + cq * 4];
            float* d = &Bs[row * LDB + cq * 4];
            d[0] = wmma::__float_to_tf32(v.x);
            d[1] = wmma::__float_to_tf32(v.y);
            d[2] = wmma::__float_to_tf32(v.z);
            d[3] = wmma::__float_to_tf32(v.w);
        }
        __syncthreads();
        #pragma unroll
        for (int kk = 0; kk < 32; kk += 8) {
            wmma::fragment<wmma::matrix_a, 16, 16, 8, wmma::precision::tf32, wmma::row_major> a;
            wmma::fragment<wmma::matrix_b, 16, 16, 8, wmma::precision::tf32, wmma::row_major> b0, b1;
            wmma::load_matrix_sync(a, &As[warpRow * LDA + kk], LDA);
            wmma::load_matrix_sync(b0, &Bs[kk * LDB + warpCol], LDB);
            wmma::load_matrix_sync(b1, &Bs[kk * LDB + warpCol + 16], LDB);
            wmma::mma_sync(acc0, a, b0, acc0);
            wmma::mma_sync(acc1, a, b1, acc1);
        }
        __syncthreads();
    }

    wmma::store_matrix_sync(&sOut[warpRow * LDO + warpCol],      acc0, LDO, wmma::mem_row_major);
    wmma::store_matrix_sync(&sOut[warpRow * LDO + warpCol + 16], acc1, LDO, wmma::mem_row_major);
    __syncthreads();
    #pragma unroll
    for (int f = tid; f < 1024; f += 256) {
        int row = f >> 4, cq = f & 15;
        if (rowBase + row < n) {
            float4 v = *(float4*)&sOut[row * LDO + cq * 4];
            if (bias) {
                float4 b = *(const float4*)&bias[colB + cq * 4];
                v.x += b.x; v.y += b.y; v.z += b.z; v.w += b.w;
            }
            *(float4*)&Cmat[(size_t)(rowBase + row) * Cout + colB + cq * 4] = v;
        }
    }
}

__global__ void gemm_tf32_kernel(const float* __restrict__ X,
                                 const float* __restrict__ W,
                                 const float* __restrict__ bias,
                                 float* __restrict__ Cmat,
                                 int n, int K, int Cout) {
    __shared__ float sm[SM_GEMM];
    gemm_body(sm, X, W, bias, Cmat, n, K, Cout, blockIdx.x, blockIdx.y);
}

// ---------------- CSR scatter + layer-1 GEMM (fused) -------------------------
__global__ void scatter_gemm_kernel(const int* __restrict__ ei,
                                    const float* __restrict__ X) {
    __shared__ float sm[SM_GEMM];
    if (blockIdx.x < SCAT_BLOCKS) {
        int e = blockIdx.x * blockDim.x + threadIdx.x;
        if (e >= EE) return;
        int dst = ei[EE + e];
        int pos = atomicAdd(&g_cursor[dst], 1);
        g_csr_se[pos] = make_int2(ei[e], e);
    } else {
        int gb = blockIdx.x - SCAT_BLOCKS;
        int colTile = gb / ROW_BLOCKS;
        int rowTile = gb - colTile * ROW_BLOCKS;
        gemm_body(sm, X, g_Wp1, g_bp1, g_xlr, NN, DIN, 128, rowTile, colTile);
    }
}

// ---------------- ewe GEMM standalone (wmma, fp16 out, both layers) ----------
__global__ __launch_bounds__(256)
void ewe_kernel(const float* __restrict__ eattr) {
    __shared__ float sm[SM_EWE2];
    float* As   = sm;
    float* Bs   = sm + 64 * LDA2;
    float* sOut = sm + 64 * LDA2 + 2 * 16 * LDB;

    int tid = threadIdx.x;
    int lane = tid & 31;
    int eBase = blockIdx.x * 64;

    {
        int row = tid >> 2, kq = tid & 3;
        float4 v = *(const float4*)&eattr[(size_t)(eBase + row) * 16 + kq * 4];
        float* d = &As[row * LDA2 + kq * 4];
        d[0] = wmma::__float_to_tf32(v.x);
        d[1] = wmma::__float_to_tf32(v.y);
        d[2] = wmma::__float_to_tf32(v.z);
        d[3] = wmma::__float_to_tf32(v.w);
    }
    {
        #pragma unroll
        for (int f = tid; f < 512; f += 256) {
            int half = f >> 8;
            int r = (f >> 4) & 15;
            int cq = f & 15;
            float4 v = *(const float4*)&g_Wep[r * 128 + half * 64 + cq * 4];
            float* d = &Bs[half * 16 * LDB + r * LDB + cq * 4];
            d[0] = wmma::__float_to_tf32(v.x);
            d[1] = wmma::__float_to_tf32(v.y);
            d[2] = wmma::__float_to_tf32(v.z);
            d[3] = wmma::__float_to_tf32(v.w);
        }
    }
    __syncthreads();

    int warpId = tid >> 5;
    int warpRow = (warpId & 3) * 16;
    int warpCol = (warpId >> 2) * 32;

    #pragma unroll
    for (int half = 0; half < 2; half++) {
        const float* Bh = Bs + half * 16 * LDB;
        wmma::fragment<wmma::accumulator, 16, 16, 8, float> acc0, acc1;
        wmma::fill_fragment(acc0, 0.f);
        wmma::fill_fragment(acc1, 0.f);
        #pragma unroll
        for (int kk = 0; kk < 16; kk += 8) {
            wmma::fragment<wmma::matrix_a, 16, 16, 8, wmma::precision::tf32, wmma::row_major> a;
            wmma::fragment<wmma::matrix_b, 16, 16, 8, wmma::precision::tf32, wmma::row_major> b0, b1;
            wmma::load_matrix_sync(a, &As[warpRow * LDA2 + kk], LDA2);
            wmma::load_matrix_sync(b0, &Bh[kk * LDB + warpCol], LDB);
            wmma::load_matrix_sync(b1, &Bh[kk * LDB + warpCol + 16], LDB);
            wmma::mma_sync(acc0, a, b0, acc0);
            wmma::mma_sync(acc1, a, b1, acc1);
        }
        wmma::store_matrix_sync(&sOut[warpRow * LDO + warpCol],      acc0, LDO, wmma::mem_row_major);
        wmma::store_matrix_sync(&sOut[warpRow * LDO + warpCol + 16], acc1, LDO, wmma::mem_row_major);
        __syncwarp();
        __half* out = half ? g_ewe2 : g_ewe1;
        #pragma unroll
        for (int q = 0; q < 4; q++) {
            int slot = q * 32 + lane;
            int row = warpRow + (slot >> 3);
            int col = warpCol + (slot & 7) * 4;
            float4 v = *(float4*)&sOut[row * LDO + col];
            __half2 h0 = __float22half2_rn(make_float2(v.x, v.y));
            __half2 h1 = __float22half2_rn(make_float2(v.z, v.w));
            uint2 pkd = make_uint2(*(unsigned*)&h0, *(unsigned*)&h1);
            *(uint2*)&out[(size_t)(eBase + row) * 64 + col] = pkd;
        }
        __syncwarp();
    }
}

// ---------------- fused GAT layer: warp/node, fp16 ewe by eid, 2-edge unroll -
__global__ __launch_bounds__(256)
void gat_layer_kernel(const __half* __restrict__ ewe,
                      const float* __restrict__ att,
                      const float* __restrict__ bias,
                      float* __restrict__ outbuf,
                      int doElu) {
    int lane = threadIdx.x & 31;
    int node = (blockIdx.x * blockDim.x + threadIdx.x) >> 5;
    if (node >= NN) return;

    float2 a2 = ((const float2*)att)[lane];
    float2 b2 = ((const float2*)bias)[lane];
    const float2* xlr2 = (const float2*)g_xlr;
    const __half2* ewe2 = (const __half2*)ewe;

    int start = g_rowptr[node], end = g_rowptr[node + 1];
    float2 rf  = xlr2[node * 64 + 32 + lane];
    float2 vSf = xlr2[node * 64 + lane];
    ull r2  = pack2(rf.x, rf.y);
    ull vS2 = pack2(vSf.x, vSf.y);

    float amax = -INFINITY, den = 0.f;
    ull acc = 0, wsum = 0;

    ull vA = 0, wA = 0, vB = 0, wB = 0;
    if (start < end) {
        int2 se = g_csr_se[start];
        float2 t = xlr2[se.x * 64 + lane];            vA = pack2(t.x, t.y);
        float2 u = __half22float2(ewe2[(size_t)se.y * 32 + lane]); wA = pack2(u.x, u.y);
    }
    if (start + 1 < end) {
        int2 se = g_csr_se[start + 1];
        float2 t = xlr2[se.x * 64 + lane];            vB = pack2(t.x, t.y);
        float2 u = __half22float2(ewe2[(size_t)se.y * 32 + lane]); wB = pack2(u.x, u.y);
    }

    int p = start;
    for (; p + 1 < end; p += 2) {
        ull v0 = vA, w0 = wA, v1 = vB, w1 = wB;
        if (p + 2 < end) {
            int2 se = g_csr_se[p + 2];
            float2 t = xlr2[se.x * 64 + lane];            vA = pack2(t.x, t.y);
            float2 u = __half22float2(ewe2[(size_t)se.y * 32 + lane]); wA = pack2(u.x, u.y);
        }
        if (p + 3 < end) {
            int2 se = g_csr_se[p + 3];
            float2 t = xlr2[se.x * 64 + lane];            vB = pack2(t.x, t.y);
            float2 u = __half22float2(ewe2[(size_t)se.y * 32 + lane]); wB = pack2(u.x, u.y);
        }
        wsum = add2(wsum, add2(w0, w1));
        ull m0 = add2(add2(v0, r2), w0);
        ull m1 = add2(add2(v1, r2), w1);
        float m0x, m0y, m1x, m1y;
        unpack2(m0, m0x, m0y);
        unpack2(m1, m1x, m1y);
        float pk0 = lrelu(m0x) * a2.x + lrelu(m0y) * a2.y;
        float pk1 = lrelu(m1x) * a2.x + lrelu(m1y) * a2.y;
        #pragma unroll
        for (int o = 16; o; o >>= 1) {
            pk0 += __shfl_xor_sync(0xffffffffu, pk0, o);
            pk1 += __shfl_xor_sync(0xffffffffu, pk1, o);
        }
        float pm = fmaxf(pk0, pk1);
        if (pm > amax) {
            float f = __expf(amax - pm);
            den *= f;
            acc = mul2(acc, pack2(f, f));
            amax = pm;
        }
        float e0 = __expf(pk0 - amax), e1 = __expf(pk1 - amax);
        den += e0 + e1;
        acc = ffma2(pack2(e0, e0), v0, acc);
        acc = ffma2(pack2(e1, e1), v1, acc);
    }
    if (p < end) {
        wsum = add2(wsum, wA);
        ull m0 = add2(add2(vA, r2), wA);
        float m0x, m0y;
        unpack2(m0, m0x, m0y);
        float pk0 = lrelu(m0x) * a2.x + lrelu(m0y) * a2.y;
        #pragma unroll
        for (int o = 16; o; o >>= 1) pk0 += __shfl_xor_sync(0xffffffffu, pk0, o);
        if (pk0 > amax) {
            float f = __expf(amax - pk0);
            den *= f;
            acc = mul2(acc, pack2(f, f));
            amax = pk0;
        }
        float e0 = __expf(pk0 - amax);
        den += e0;
        acc = ffma2(pack2(e0, e0), vA, acc);
    }

    float invdeg = 1.f / fmaxf((float)(end - start), 1.f);
    ull mS = add2(add2(vS2, r2), mul2(wsum, pack2(invdeg, invdeg)));
    float msx, msy;
    unpack2(mS, msx, msy);
    float pS = lrelu(msx) * a2.x + lrelu(msy) * a2.y;
    #pragma unroll
    for (int o = 16; o; o >>= 1) pS += __shfl_xor_sync(0xffffffffu, pS, o);
    if (pS > amax) {
        float f = __expf(amax - pS);
        den *= f;
        acc = mul2(acc, pack2(f, f));
        amax = pS;
    }
    float eS = __expf(pS - amax);
    den += eS;
    acc = ffma2(pack2(eS, eS), vS2, acc);

    float inv = 1.f / den;
    float accx, accy;
    unpack2(acc, accx, accy);
    float ox = accx * inv + b2.x;
    float oy = accy * inv + b2.y;
    if (doElu) { ox = eluf(ox); oy = eluf(oy); }
    ((float2*)outbuf)[node * 32 + lane] = make_float2(ox, oy);
}

// ---------------- edge classifier: pair + depth-1 prefetch, fp16 weights -----
__global__ __launch_bounds__(128)
void classifier_kernel(const float* __restrict__ eattr,
                       const int* __restrict__ ei,
                       const float* __restrict__ Cw1c,   // [16][256]
                       const float* __restrict__ Cb1,
                       const float* __restrict__ Cw2,
                       const float* __restrict__ Cb2,
                       float* __restrict__ out) {
    int lane = threadIdx.x & 31;
    int c0 = 4 * lane;
    __half2 wh[DE][4];
    #pragma unroll
    for (int k = 0; k < DE; k++) {
        float4 A = *(const float4*)&Cw1c[k * HID + c0];
        float4 B = *(const float4*)&Cw1c[k * HID + 128 + c0];
        wh[k][0] = __floats2half2_rn(A.x, A.y);
        wh[k][1] = __floats2half2_rn(A.z, A.w);
        wh[k][2] = __floats2half2_rn(B.x, B.y);
        wh[k][3] = __floats2half2_rn(B.z, B.w);
    }
    float4 b0 = *(const float4*)&Cb1[c0];
    float4 b1 = *(const float4*)&Cb1[128 + c0];
    float4 c20 = *(const float4*)&Cw2[c0];
    float4 c21 = *(const float4*)&Cw2[128 + c0];
    float cb2 = Cb2[0];

    const float4* P  = (const float4*)g_P12;
    const float4* EA = (const float4*)eattr;
    int pairGid = (blockIdx.x * blockDim.x + threadIdx.x) >> 5;
    int pairsTotal = (gridDim.x * blockDim.x) >> 5;
    const int NPAIR = EE / 2;

    // prefetch buffers (next pair)
    float4 n1a0, n1b0, n2a0, n2b0, n1a1, n1b1, n2a1, n2b1;
    if (pairGid < NPAIR) {
        int f0 = 2 * pairGid, f1 = f0 + 1;
        int s0 = ei[f0], d0 = ei[EE + f0];
        int s1 = ei[f1], d1 = ei[EE + f1];
        n1a0 = P[(size_t)s0 * 128 + lane];
        n1b0 = P[(size_t)s0 * 128 + 32 + lane];
        n2a0 = P[(size_t)d0 * 128 + 64 + lane];
        n2b0 = P[(size_t)d0 * 128 + 96 + lane];
        n1a1 = P[(size_t)s1 * 128 + lane];
        n1b1 = P[(size_t)s1 * 128 + 32 + lane];
        n2a1 = P[(size_t)d1 * 128 + 64 + lane];
        n2b1 = P[(size_t)d1 * 128 + 96 + lane];
    }

    for (int pr = pairGid; pr < NPAIR; pr += pairsTotal) {
        int e0 = 2 * pr, e1 = e0 + 1;
        // consume prefetched values
        float4 p1a0 = n1a0, p1b0 = n1b0, p2a0 = n2a0, p2b0 = n2b0;
        float4 p1a1 = n1a1, p1b1 = n1b1, p2a1 = n2a1, p2b1 = n2b1;
        // issue next pair's gathers now (fly during compute)
        int prn = pr + pairsTotal;
        if (prn < NPAIR) {
            int f0 = 2 * prn, f1 = f0 + 1;
            int s0 = ei[f0], d0 = ei[EE + f0];
            int s1 = ei[f1], d1 = ei[EE + f1];
            n1a0 = P[(size_t)s0 * 128 + lane];
            n1b0 = P[(size_t)s0 * 128 + 32 + lane];
            n2a0 = P[(size_t)d0 * 128 + 64 + lane];
            n2b0 = P[(size_t)d0 * 128 + 96 + lane];
            n1a1 = P[(size_t)s1 * 128 + lane];
            n1b1 = P[(size_t)s1 * 128 + 32 + lane];
            n2a1 = P[(size_t)d1 * 128 + 64 + lane];
            n2b1 = P[(size_t)d1 * 128 + 96 + lane];
        }
        // two independent fp16 HFMA chains on ea (uniform loads, sequential)
        __half2 x0 = __float2half2_rn(0.f), x1 = x0, x2 = x0, x3 = x0;
        __half2 y0 = x0, y1 = x0, y2 = x0, y3 = x0;
        #pragma unroll
        for (int kq = 0; kq < 4; kq++) {
            float4 ea0 = EA[(size_t)e0 * 4 + kq];
            float4 ea1 = EA[(size_t)e1 * 4 + kq];
            const float* e0p = (const float*)&ea0;
            const float* e1p = (const float*)&ea1;
            #pragma unroll
            for (int j = 0; j < 4; j++) {
                int k = kq * 4 + j;
                __half2 s0 = __float2half2_rn(e0p[j]);
                __half2 s1 = __float2half2_rn(e1p[j]);
                x0 = __hfma2(s0, wh[k][0], x0);
                x1 = __hfma2(s0, wh[k][1], x1);
                x2 = __hfma2(s0, wh[k][2], x2);
                x3 = __hfma2(s0, wh[k][3], x3);
                y0 = __hfma2(s1, wh[k][0], y0);
                y1 = __hfma2(s1, wh[k][1], y1);
                y2 = __hfma2(s1, wh[k][2], y2);
                y3 = __hfma2(s1, wh[k][3], y3);
            }
        }
        float2 f0v = __half22float2(x0), f1v = __half22float2(x1);
        float2 f2v = __half22float2(x2), f3v = __half22float2(x3);
        float2 g0v = __half22float2(y0), g1v = __half22float2(y1);
        float2 g2v = __half22float2(y2), g3v = __half22float2(y3);
        float acc0 =
              eluf(f0v.x + p1a0.x + p2a0.x + b0.x) * c20.x
            + eluf(f0v.y + p1a0.y + p2a0.y + b0.y) * c20.y
            + eluf(f1v.x + p1a0.z + p2a0.z + b0.z) * c20.z
            + eluf(f1v.y + p1a0.w + p2a0.w + b0.w) * c20.w
            + eluf(f2v.x + p1b0.x + p2b0.x + b1.x) * c21.x
            + eluf(f2v.y + p1b0.y + p2b0.y + b1.y) * c21.y
            + eluf(f3v.x + p1b0.z + p2b0.z + b1.z) * c21.z
            + eluf(f3v.y + p1b0.w + p2b0.w + b1.w) * c21.w;
        float acc1 =
              eluf(g0v.x + p1a1.x + p2a1.x + b0.x) * c20.x
            + eluf(g0v.y + p1a1.y + p2a1.y + b0.y) * c20.y
            + eluf(g1v.x + p1a1.z + p2a1.z + b0.z) * c20.z
            + eluf(g1v.y + p1a1.w + p2a1.w + b0.w) * c20.w
            + eluf(g2v.x + p1b1.x + p2b1.x + b1.x) * c21.x
            + eluf(g2v.y + p1b1.y + p2b1.y + b1.y) * c21.y
            + eluf(g3v.x + p1b1.z + p2b1.z + b1.z) * c21.z
            + eluf(g3v.y + p1b1.w + p2b1.w + b1.w) * c21.w;
        #pragma unroll
        for (int o = 16; o; o >>= 1) {
            acc0 += __shfl_xor_sync(0xffffffffu, acc0, o);
            acc1 += __shfl_xor_sync(0xffffffffu, acc1, o);
        }
        if (lane == 0) {
            out[e0] = acc0 + cb2;
            out[e1] = acc1 + cb2;
        }
    }
}

// ---------------- host orchestration ----------------------------------------
static inline int ceil_div(int a, int b) { return (a + b - 1) / b; }

extern "C" void kernel_launch(void* const* d_in, const int* in_sizes, int n_in,
                              void* d_out, int out_size) {
    const float* x     = (const float*)d_in[0];
    const float* eattr = (const float*)d_in[1];
    const float* W1l   = (const float*)d_in[2];
    const float* b1l   = (const float*)d_in[3];
    const float* W1r   = (const float*)d_in[4];
    const float* b1r   = (const float*)d_in[5];
    const float* We1   = (const float*)d_in[6];
    const float* att1  = (const float*)d_in[7];
    const float* bias1 = (const float*)d_in[8];
    const float* W2l   = (const float*)d_in[9];
    const float* b2l   = (const float*)d_in[10];
    const float* W2r   = (const float*)d_in[11];
    const float* b2r   = (const float*)d_in[12];
    const float* We2   = (const float*)d_in[13];
    const float* att2  = (const float*)d_in[14];
    const float* bias2 = (const float*)d_in[15];
    // d_in[16..19] (Aw1/Ab1/Aw2/Ab2): softmax over a single column == 1 -> unused
    const float* Cw1   = (const float*)d_in[20];
    const float* Cb1   = (const float*)d_in[21];
    const float* Cw2   = (const float*)d_in[22];
    const float* Cb2   = (const float*)d_in[23];
    const int*   ei    = (const int*)  d_in[24];
    float* out = (float*)d_out;

    float *d_h, *d_h2, *d_P12, *d_Wp2, *d_WpC, *d_bp2, *d_xlr;
    __half *d_ewe1, *d_ewe2;
    cudaGetSymbolAddress((void**)&d_h,    g_h);
    cudaGetSymbolAddress((void**)&d_h2,   g_h2);
    cudaGetSymbolAddress((void**)&d_P12,  g_P12);
    cudaGetSymbolAddress((void**)&d_Wp2,  g_Wp2);
    cudaGetSymbolAddress((void**)&d_WpC,  g_WpC);
    cudaGetSymbolAddress((void**)&d_bp2,  g_bp2);
    cudaGetSymbolAddress((void**)&d_xlr,  g_xlr);
    cudaGetSymbolAddress((void**)&d_ewe1, g_ewe1);
    cudaGetSymbolAddress((void**)&d_ewe2, g_ewe2);

    const int TB = 256;
    int gatBlocks = ceil_div(NN * 32, TB);

    // 1: pack weights + histogram
    prep_kernel<<<ceil_div(EE, TB), TB>>>(W1l, W1r, b1l, b1r, W2l, W2r, b2l, b2r,
                                          We1, We2, Cw1, ei);
    // 2-3: parallel scan (block sums + offsets)
    scan_blocksum_kernel<<<SCAN_BLOCKS, 1024>>>();
    scan_offsets_kernel<<<1, 64>>>(SCAN_BLOCKS);
    // 4: ewe GEMM (independent of scan)  (ncu capture slot)
    ewe_kernel<<<EWE_BLOCKS, 256>>>(eattr);
    // 5: scan finalize (+ re-zero g_cnt)
    scan_final_kernel<<<SCAN_BLOCKS, 1024>>>();
    // 6: CSR scatter + layer-1 GEMM fused
    scatter_gemm_kernel<<<SCAT_BLOCKS + 2 * ROW_BLOCKS, 256>>>(ei, x);
    // 7: GAT layer 1
    gat_layer_kernel<<<gatBlocks, TB>>>(d_ewe1, att1, bias1, d_h, 1);
    // 8-9: layer 2
    gemm_tf32_kernel<<<dim3(ROW_BLOCKS, 2), 256>>>(d_h, d_Wp2, d_bp2, d_xlr, NN, C, 128);
    gat_layer_kernel<<<gatBlocks, TB>>>(d_ewe2, att2, bias2, d_h2, 0);
    // 10-11: classifier
    gemm_tf32_kernel<<<dim3(ROW_BLOCKS, 8), 256>>>(d_h2, d_WpC, nullptr, d_P12, NN, C, 512);
    classifier_kernel<<<2368, 128>>>(eattr, ei, Cw1 + 2 * C * HID, Cb1, Cw2, Cb2, out);
}

// round 17
// speedup vs baseline: 1.1836x; 1.0068x over previous
#include <cuda_runtime.h>
#include <cuda_fp16.h>
#include <mma.h>
#include <math.h>

using namespace nvcuda;

constexpr int NN   = 50000;
constexpr int EE   = 800000;
constexpr int DIN  = 128;
constexpr int DE   = 16;
constexpr int C    = 64;
constexpr int HID  = 256;
constexpr float NEG = 0.2f;

constexpr int SCAT_BLOCKS = (EE + 255) / 256;        // 3125
constexpr int ROW_BLOCKS  = (NN + 63) / 64;          // 782
constexpr int EWE_BLOCKS  = EE / 64;                 // 12500 (exact)
constexpr int SCAN_BLOCKS = (NN + 1023) / 1024;      // 49

// ---------------- device scratch --------------------------------------------
__device__ int    g_cnt[NN];          // zero at load; re-zeroed by scan_final
__device__ int    g_rowptr[NN + 1];
__device__ int    g_cursor[NN];
__device__ int    g_bsum[64];
__device__ int    g_boff[64];
__device__ int2   g_csr_se[EE];       // (src, eid) per CSR slot
__device__ __half g_ewe1[(size_t)EE * 64];   // layer-1 e@We, fp16
__device__ __half g_ewe2[(size_t)EE * 64];   // layer-2 e@We, fp16
__device__ float  g_xlr[NN * 128];    // cols 0..63 = xl, 64..127 = xr
__device__ float  g_h[NN * C];
__device__ float  g_h2[NN * C];
__device__ float  g_P12[NN * 512];    // cols 0..255 = P1, 256..511 = P2
__device__ float  g_Wp1[DIN * 128];
__device__ float  g_Wp2[C * 128];
__device__ float  g_WpC[C * 512];
__device__ float  g_Wep[DE * 128];    // [We1 | We2]
__device__ float  g_bp1[128];
__device__ float  g_bp2[128];

__device__ __forceinline__ float lrelu(float x) { return x > 0.f ? x : NEG * x; }
__device__ __forceinline__ float eluf(float x)  { return x > 0.f ? x : __expf(x) - 1.f; }

typedef unsigned long long ull;
__device__ __forceinline__ ull pack2(float lo, float hi) {
    ull r;
    asm("mov.b64 %0, {%1, %2};" : "=l"(r) : "f"(lo), "f"(hi));
    return r;
}
__device__ __forceinline__ void unpack2(ull v, float& lo, float& hi) {
    asm("mov.b64 {%0, %1}, %2;" : "=f"(lo), "=f"(hi) : "l"(v));
}
__device__ __forceinline__ ull ffma2(ull a, ull b, ull c) {
    ull d;
    asm("fma.rn.f32x2 %0, %1, %2, %3;" : "=l"(d) : "l"(a), "l"(b), "l"(c));
    return d;
}
__device__ __forceinline__ ull add2(ull a, ull b) {
    ull d;
    asm("add.rn.f32x2 %0, %1, %2;" : "=l"(d) : "l"(a), "l"(b));
    return d;
}
__device__ __forceinline__ ull mul2(ull a, ull b) {
    ull d;
    asm("mul.rn.f32x2 %0, %1, %2;" : "=l"(d) : "l"(a), "l"(b));
    return d;
}
__device__ __forceinline__ void cp16(void* smem, const void* gmem) {
    unsigned saddr = (unsigned)__cvta_generic_to_shared(smem);
    asm volatile("cp.async.cg.shared.global [%0], [%1], 16;" :: "r"(saddr), "l"(gmem));
}
__device__ __forceinline__ void cp_commit() {
    asm volatile("cp.async.commit_group;");
}

// ---------------- launch 1: pack weights + degree histogram ------------------
__global__ void prep_kernel(const float* __restrict__ W1l, const float* __restrict__ W1r,
                            const float* __restrict__ b1l, const float* __restrict__ b1r,
                            const float* __restrict__ W2l, const float* __restrict__ W2r,
                            const float* __restrict__ b2l, const float* __restrict__ b2r,
                            const float* __restrict__ We1, const float* __restrict__ We2,
                            const float* __restrict__ Cw1,
                            const int* __restrict__ ei) {
    int i = blockIdx.x * blockDim.x + threadIdx.x;
    if (i < EE) atomicAdd(&g_cnt[ei[EE + i]], 1);
    if (i < DIN * 128) {
        int k = i >> 7, c = i & 127;
        g_Wp1[i] = (c < 64) ? W1l[k * 64 + c] : W1r[k * 64 + c - 64];
    }
    if (i < DE * 128) {
        int k = i >> 7, c = i & 127;
        g_Wep[i] = (c < 64) ? We1[k * 64 + c] : We2[k * 64 + c - 64];
    }
    int j = i - DIN * 128;
    if (j >= 0 && j < C * 128) {
        int k = j >> 7, c = j & 127;
        g_Wp2[j] = (c < 64) ? W2l[k * 64 + c] : W2r[k * 64 + c - 64];
    }
    int l = i - DIN * 128 - C * 128;
    if (l >= 0 && l < C * 512) {
        int k = l >> 9, c = l & 511;
        g_WpC[l] = (c < 256) ? Cw1[k * 256 + c] : Cw1[(64 + k) * 256 + c - 256];
    }
    if (i < 128) {
        g_bp1[i] = (i < 64) ? b1l[i] : b1r[i - 64];
        g_bp2[i] = (i < 64) ? b2l[i] : b2r[i - 64];
    }
}

// ---------------- parallel 3-kernel scan -------------------------------------
__global__ void scan_blocksum_kernel() {
    __shared__ int sw[32];
    int i = blockIdx.x * 1024 + threadIdx.x;
    int v = (i < NN) ? g_cnt[i] : 0;
    #pragma unroll
    for (int o = 16; o; o >>= 1) v += __shfl_xor_sync(0xffffffffu, v, o);
    if ((threadIdx.x & 31) == 0) sw[threadIdx.x >> 5] = v;
    __syncthreads();
    if (threadIdx.x < 32) {
        int s = sw[threadIdx.x];
        #pragma unroll
        for (int o = 16; o; o >>= 1) s += __shfl_xor_sync(0xffffffffu, s, o);
        if (threadIdx.x == 0) g_bsum[blockIdx.x] = s;
    }
}

__global__ void scan_offsets_kernel(int nblocks) {
    __shared__ int s[64];
    int t = threadIdx.x;
    s[t] = (t < nblocks) ? g_bsum[t] : 0;
    __syncthreads();
    #pragma unroll
    for (int off = 1; off < 64; off <<= 1) {
        int v = (t >= off) ? s[t - off] : 0;
        __syncthreads();
        s[t] += v;
        __syncthreads();
    }
    if (t < nblocks) g_boff[t] = s[t] - g_bsum[t];
}

__global__ void scan_final_kernel() {
    __shared__ int s[1024];
    int t = threadIdx.x;
    int i = blockIdx.x * 1024 + t;
    int v = 0;
    if (i < NN) { v = g_cnt[i]; g_cnt[i] = 0; }
    s[t] = v;
    __syncthreads();
    #pragma unroll
    for (int off = 1; off < 1024; off <<= 1) {
        int u = (t >= off) ? s[t - off] : 0;
        __syncthreads();
        s[t] += u;
        __syncthreads();
    }
    int excl = g_boff[blockIdx.x] + s[t] - v;
    if (i < NN) {
        g_rowptr[i] = excl;
        g_cursor[i] = excl;
        if (i == NN - 1) g_rowptr[NN] = excl + v;
    }
}

// ---------------- tf32 WMMA GEMM body ----------------------------------------
constexpr int LDA = 40;
constexpr int LDB = 72;
constexpr int LDO = 72;
constexpr int LDA2 = 24;

constexpr int SM_GEMM = 64 * LDA + 32 * LDB;                      // 4864
constexpr int SM_EWE2 = 64 * LDA2 + 2 * 16 * LDB + 64 * LDO;      // 8448

__device__ void gemm_body(float* sm,
                          const float* __restrict__ X,
                          const float* __restrict__ W,
                          const float* __restrict__ bias,
                          float* __restrict__ Cmat,
                          int n, int K, int Cout,
                          int rowTile, int colTile) {
    float* As = sm;
    float* Bs = sm + 64 * LDA;
    float* sOut = sm;

    int tid = threadIdx.x;
    int warpId = tid >> 5;
    int rowBase = rowTile * 64;
    int colB    = colTile * 64;
    int warpRow = (warpId & 3) * 16;
    int warpCol = (warpId >> 2) * 32;

    wmma::fragment<wmma::accumulator, 16, 16, 8, float> acc0, acc1;
    wmma::fill_fragment(acc0, 0.f);
    wmma::fill_fragment(acc1, 0.f);

    for (int kt = 0; kt < K; kt += 32) {
        #pragma unroll
        for (int f = tid; f < 512; f += 256) {
            int row = f >> 3, kq = f & 7;
            float4 v = make_float4(0.f, 0.f, 0.f, 0.f);
            if (rowBase + row < n)
                v = *(const float4*)&X[(size_t)(rowBase + row) * K + kt + kq * 4];
            float* d = &As[row * LDA + kq * 4];
            d[0] = wmma::__float_to_tf32(v.x);
            d[1] = wmma::__float_to_tf32(v.y);
            d[2] = wmma::__float_to_tf32(v.z);
            d[3] = wmma::__float_to_tf32(v.w);
        }
        #pragma unroll
        for (int f = tid; f < 512; f += 256) {
            int row = f >> 4, cq = f & 15;
            float4 v = *(const float4*)&W[(size_t)(kt + row) * Cout + colB + cq * 4];
            float* d = &Bs[row * LDB + cq * 4];
            d[0] = wmma::__float_to_tf32(v.x);
            d[1] = wmma::__float_to_tf32(v.y);
            d[2] = wmma::__float_to_tf32(v.z);
            d[3] = wmma::__float_to_tf32(v.w);
        }
        __syncthreads();
        #pragma unroll
        for (int kk = 0; kk < 32; kk += 8) {
            wmma::fragment<wmma::matrix_a, 16, 16, 8, wmma::precision::tf32, wmma::row_major> a;
            wmma::fragment<wmma::matrix_b, 16, 16, 8, wmma::precision::tf32, wmma::row_major> b0, b1;
            wmma::load_matrix_sync(a, &As[warpRow * LDA + kk], LDA);
            wmma::load_matrix_sync(b0, &Bs[kk * LDB + warpCol], LDB);
            wmma::load_matrix_sync(b1, &Bs[kk * LDB + warpCol + 16], LDB);
            wmma::mma_sync(acc0, a, b0, acc0);
            wmma::mma_sync(acc1, a, b1, acc1);
        }
        __syncthreads();
    }

    wmma::store_matrix_sync(&sOut[warpRow * LDO + warpCol],      acc0, LDO, wmma::mem_row_major);
    wmma::store_matrix_sync(&sOut[warpRow * LDO + warpCol + 16], acc1, LDO, wmma::mem_row_major);
    __syncthreads();
    #pragma unroll
    for (int f = tid; f < 1024; f += 256) {
        int row = f >> 4, cq = f & 15;
        if (rowBase + row < n) {
            float4 v = *(float4*)&sOut[row * LDO + cq * 4];
            if (bias) {
                float4 b = *(const float4*)&bias[colB + cq * 4];
                v.x += b.x; v.y += b.y; v.z += b.z; v.w += b.w;
            }
            *(float4*)&Cmat[(size_t)(rowBase + row) * Cout + colB + cq * 4] = v;
        }
    }
}

__global__ void gemm_tf32_kernel(const float* __restrict__ X,
                                 const float* __restrict__ W,
                                 const float* __restrict__ bias,
                                 float* __restrict__ Cmat,
                                 int n, int K, int Cout) {
    __shared__ float sm[SM_GEMM];
    gemm_body(sm, X, W, bias, Cmat, n, K, Cout, blockIdx.x, blockIdx.y);
}

// ---------------- CSR scatter + layer-1 GEMM (fused) -------------------------
__global__ void scatter_gemm_kernel(const int* __restrict__ ei,
                                    const float* __restrict__ X) {
    __shared__ float sm[SM_GEMM];
    if (blockIdx.x < SCAT_BLOCKS) {
        int e = blockIdx.x * blockDim.x + threadIdx.x;
        if (e >= EE) return;
        int dst = ei[EE + e];
        int pos = atomicAdd(&g_cursor[dst], 1);
        g_csr_se[pos] = make_int2(ei[e], e);
    } else {
        int gb = blockIdx.x - SCAT_BLOCKS;
        int colTile = gb / ROW_BLOCKS;
        int rowTile = gb - colTile * ROW_BLOCKS;
        gemm_body(sm, X, g_Wp1, g_bp1, g_xlr, NN, DIN, 128, rowTile, colTile);
    }
}

// ---------------- ewe GEMM standalone (wmma, fp16 out, both layers) ----------
__global__ __launch_bounds__(256)
void ewe_kernel(const float* __restrict__ eattr) {
    __shared__ float sm[SM_EWE2];
    float* As   = sm;
    float* Bs   = sm + 64 * LDA2;
    float* sOut = sm + 64 * LDA2 + 2 * 16 * LDB;

    int tid = threadIdx.x;
    int lane = tid & 31;
    int eBase = blockIdx.x * 64;

    {
        int row = tid >> 2, kq = tid & 3;
        float4 v = *(const float4*)&eattr[(size_t)(eBase + row) * 16 + kq * 4];
        float* d = &As[row * LDA2 + kq * 4];
        d[0] = wmma::__float_to_tf32(v.x);
        d[1] = wmma::__float_to_tf32(v.y);
        d[2] = wmma::__float_to_tf32(v.z);
        d[3] = wmma::__float_to_tf32(v.w);
    }
    {
        #pragma unroll
        for (int f = tid; f < 512; f += 256) {
            int half = f >> 8;
            int r = (f >> 4) & 15;
            int cq = f & 15;
            float4 v = *(const float4*)&g_Wep[r * 128 + half * 64 + cq * 4];
            float* d = &Bs[half * 16 * LDB + r * LDB + cq * 4];
            d[0] = wmma::__float_to_tf32(v.x);
            d[1] = wmma::__float_to_tf32(v.y);
            d[2] = wmma::__float_to_tf32(v.z);
            d[3] = wmma::__float_to_tf32(v.w);
        }
    }
    __syncthreads();

    int warpId = tid >> 5;
    int warpRow = (warpId & 3) * 16;
    int warpCol = (warpId >> 2) * 32;

    #pragma unroll
    for (int half = 0; half < 2; half++) {
        const float* Bh = Bs + half * 16 * LDB;
        wmma::fragment<wmma::accumulator, 16, 16, 8, float> acc0, acc1;
        wmma::fill_fragment(acc0, 0.f);
        wmma::fill_fragment(acc1, 0.f);
        #pragma unroll
        for (int kk = 0; kk < 16; kk += 8) {
            wmma::fragment<wmma::matrix_a, 16, 16, 8, wmma::precision::tf32, wmma::row_major> a;
            wmma::fragment<wmma::matrix_b, 16, 16, 8, wmma::precision::tf32, wmma::row_major> b0, b1;
            wmma::load_matrix_sync(a, &As[warpRow * LDA2 + kk], LDA2);
            wmma::load_matrix_sync(b0, &Bh[kk * LDB + warpCol], LDB);
            wmma::load_matrix_sync(b1, &Bh[kk * LDB + warpCol + 16], LDB);
            wmma::mma_sync(acc0, a, b0, acc0);
            wmma::mma_sync(acc1, a, b1, acc1);
        }
        wmma::store_matrix_sync(&sOut[warpRow * LDO + warpCol],      acc0, LDO, wmma::mem_row_major);
        wmma::store_matrix_sync(&sOut[warpRow * LDO + warpCol + 16], acc1, LDO, wmma::mem_row_major);
        __syncwarp();
        __half* out = half ? g_ewe2 : g_ewe1;
        #pragma unroll
        for (int q = 0; q < 4; q++) {
            int slot = q * 32 + lane;
            int row = warpRow + (slot >> 3);
            int col = warpCol + (slot & 7) * 4;
            float4 v = *(float4*)&sOut[row * LDO + col];
            __half2 h0 = __float22half2_rn(make_float2(v.x, v.y));
            __half2 h1 = __float22half2_rn(make_float2(v.z, v.w));
            uint2 pkd = make_uint2(*(unsigned*)&h0, *(unsigned*)&h1);
            *(uint2*)&out[(size_t)(eBase + row) * 64 + col] = pkd;
        }
        __syncwarp();
    }
}

// ---------------- fused GAT layer: warp/node, fp16 ewe by eid, 2-edge unroll -
__global__ __launch_bounds__(256)
void gat_layer_kernel(const __half* __restrict__ ewe,
                      const float* __restrict__ att,
                      const float* __restrict__ bias,
                      float* __restrict__ outbuf,
                      int doElu) {
    int lane = threadIdx.x & 31;
    int node = (blockIdx.x * blockDim.x + threadIdx.x) >> 5;
    if (node >= NN) return;

    float2 a2 = ((const float2*)att)[lane];
    float2 b2 = ((const float2*)bias)[lane];
    const float2* xlr2 = (const float2*)g_xlr;
    const __half2* ewe2 = (const __half2*)ewe;

    int start = g_rowptr[node], end = g_rowptr[node + 1];
    float2 rf  = xlr2[node * 64 + 32 + lane];
    float2 vSf = xlr2[node * 64 + lane];
    ull r2  = pack2(rf.x, rf.y);
    ull vS2 = pack2(vSf.x, vSf.y);

    float amax = -INFINITY, den = 0.f;
    ull acc = 0, wsum = 0;

    ull vA = 0, wA = 0, vB = 0, wB = 0;
    if (start < end) {
        int2 se = g_csr_se[start];
        float2 t = xlr2[se.x * 64 + lane];            vA = pack2(t.x, t.y);
        float2 u = __half22float2(ewe2[(size_t)se.y * 32 + lane]); wA = pack2(u.x, u.y);
    }
    if (start + 1 < end) {
        int2 se = g_csr_se[start + 1];
        float2 t = xlr2[se.x * 64 + lane];            vB = pack2(t.x, t.y);
        float2 u = __half22float2(ewe2[(size_t)se.y * 32 + lane]); wB = pack2(u.x, u.y);
    }

    int p = start;
    for (; p + 1 < end; p += 2) {
        ull v0 = vA, w0 = wA, v1 = vB, w1 = wB;
        if (p + 2 < end) {
            int2 se = g_csr_se[p + 2];
            float2 t = xlr2[se.x * 64 + lane];            vA = pack2(t.x, t.y);
            float2 u = __half22float2(ewe2[(size_t)se.y * 32 + lane]); wA = pack2(u.x, u.y);
        }
        if (p + 3 < end) {
            int2 se = g_csr_se[p + 3];
            float2 t = xlr2[se.x * 64 + lane];            vB = pack2(t.x, t.y);
            float2 u = __half22float2(ewe2[(size_t)se.y * 32 + lane]); wB = pack2(u.x, u.y);
        }
        wsum = add2(wsum, add2(w0, w1));
        ull m0 = add2(add2(v0, r2), w0);
        ull m1 = add2(add2(v1, r2), w1);
        float m0x, m0y, m1x, m1y;
        unpack2(m0, m0x, m0y);
        unpack2(m1, m1x, m1y);
        float pk0 = lrelu(m0x) * a2.x + lrelu(m0y) * a2.y;
        float pk1 = lrelu(m1x) * a2.x + lrelu(m1y) * a2.y;
        #pragma unroll
        for (int o = 16; o; o >>= 1) {
            pk0 += __shfl_xor_sync(0xffffffffu, pk0, o);
            pk1 += __shfl_xor_sync(0xffffffffu, pk1, o);
        }
        float pm = fmaxf(pk0, pk1);
        if (pm > amax) {
            float f = __expf(amax - pm);
            den *= f;
            acc = mul2(acc, pack2(f, f));
            amax = pm;
        }
        float e0 = __expf(pk0 - amax), e1 = __expf(pk1 - amax);
        den += e0 + e1;
        acc = ffma2(pack2(e0, e0), v0, acc);
        acc = ffma2(pack2(e1, e1), v1, acc);
    }
    if (p < end) {
        wsum = add2(wsum, wA);
        ull m0 = add2(add2(vA, r2), wA);
        float m0x, m0y;
        unpack2(m0, m0x, m0y);
        float pk0 = lrelu(m0x) * a2.x + lrelu(m0y) * a2.y;
        #pragma unroll
        for (int o = 16; o; o >>= 1) pk0 += __shfl_xor_sync(0xffffffffu, pk0, o);
        if (pk0 > amax) {
            float f = __expf(amax - pk0);
            den *= f;
            acc = mul2(acc, pack2(f, f));
            amax = pk0;
        }
        float e0 = __expf(pk0 - amax);
        den += e0;
        acc = ffma2(pack2(e0, e0), vA, acc);
    }

    float invdeg = 1.f / fmaxf((float)(end - start), 1.f);
    ull mS = add2(add2(vS2, r2), mul2(wsum, pack2(invdeg, invdeg)));
    float msx, msy;
    unpack2(mS, msx, msy);
    float pS = lrelu(msx) * a2.x + lrelu(msy) * a2.y;
    #pragma unroll
    for (int o = 16; o; o >>= 1) pS += __shfl_xor_sync(0xffffffffu, pS, o);
    if (pS > amax) {
        float f = __expf(amax - pS);
        den *= f;
        acc = mul2(acc, pack2(f, f));
        amax = pS;
    }
    float eS = __expf(pS - amax);
    den += eS;
    acc = ffma2(pack2(eS, eS), vS2, acc);

    float inv = 1.f / den;
    float accx, accy;
    unpack2(acc, accx, accy);
    float ox = accx * inv + b2.x;
    float oy = accy * inv + b2.y;
    if (doElu) { ox = eluf(ox); oy = eluf(oy); }
    ((float2*)outbuf)[node * 32 + lane] = make_float2(ox, oy);
}

// ---------------- edge classifier: pair + cp.async smem double-buffer --------
__global__ __launch_bounds__(128)
void classifier_kernel(const float* __restrict__ eattr,
                       const int* __restrict__ ei,
                       const float* __restrict__ Cw1c,   // [16][256]
                       const float* __restrict__ Cb1,
                       const float* __restrict__ Cw2,
                       const float* __restrict__ Cb2,
                       float* __restrict__ out) {
    // smem: [buf][j][tid] — conflict-free LDS.128 (lanes consecutive 16B)
    __shared__ float4 sP[2][8][128];

    int tid  = threadIdx.x;
    int lane = tid & 31;
    int c0 = 4 * lane;
    __half2 wh[DE][4];
    #pragma unroll
    for (int k = 0; k < DE; k++) {
        float4 A = *(const float4*)&Cw1c[k * HID + c0];
        float4 B = *(const float4*)&Cw1c[k * HID + 128 + c0];
        wh[k][0] = __floats2half2_rn(A.x, A.y);
        wh[k][1] = __floats2half2_rn(A.z, A.w);
        wh[k][2] = __floats2half2_rn(B.x, B.y);
        wh[k][3] = __floats2half2_rn(B.z, B.w);
    }
    float4 b0 = *(const float4*)&Cb1[c0];
    float4 b1 = *(const float4*)&Cb1[128 + c0];
    float4 c20 = *(const float4*)&Cw2[c0];
    float4 c21 = *(const float4*)&Cw2[128 + c0];
    float cb2 = Cb2[0];

    const float4* P  = (const float4*)g_P12;
    const float4* EA = (const float4*)eattr;
    int pairGid = (blockIdx.x * blockDim.x + tid) >> 5;
    int pairsTotal = (gridDim.x * blockDim.x) >> 5;
    const int NPAIR = EE / 2;
    if (pairGid >= NPAIR) return;

    // issue gathers for pair pr into buffer buf
    auto issue = [&](int buf, int pr) {
        int e0 = 2 * pr, e1 = e0 + 1;
        int s0 = ei[e0], d0 = ei[EE + e0];
        int s1 = ei[e1], d1 = ei[EE + e1];
        cp16(&sP[buf][0][tid], &P[(size_t)s0 * 128 + lane]);
        cp16(&sP[buf][1][tid], &P[(size_t)s0 * 128 + 32 + lane]);
        cp16(&sP[buf][2][tid], &P[(size_t)d0 * 128 + 64 + lane]);
        cp16(&sP[buf][3][tid], &P[(size_t)d0 * 128 + 96 + lane]);
        cp16(&sP[buf][4][tid], &P[(size_t)s1 * 128 + lane]);
        cp16(&sP[buf][5][tid], &P[(size_t)s1 * 128 + 32 + lane]);
        cp16(&sP[buf][6][tid], &P[(size_t)d1 * 128 + 64 + lane]);
        cp16(&sP[buf][7][tid], &P[(size_t)d1 * 128 + 96 + lane]);
        cp_commit();
    };

    issue(0, pairGid);
    int buf = 0;
    for (int pr = pairGid; pr < NPAIR; pr += pairsTotal) {
        int e0 = 2 * pr, e1 = e0 + 1;
        int prn = pr + pairsTotal;
        bool hasNext = (prn < NPAIR);
        if (hasNext) issue(buf ^ 1, prn);
        // ea uniform loads overlap the cp.async wait
        __half2 x0 = __float2half2_rn(0.f), x1 = x0, x2 = x0, x3 = x0;
        __half2 y0 = x0, y1 = x0, y2 = x0, y3 = x0;
        #pragma unroll
        for (int kq = 0; kq < 4; kq++) {
            float4 ea0 = EA[(size_t)e0 * 4 + kq];
            float4 ea1 = EA[(size_t)e1 * 4 + kq];
            const float* e0p = (const float*)&ea0;
            const float* e1p = (const float*)&ea1;
            #pragma unroll
            for (int j = 0; j < 4; j++) {
                int k = kq * 4 + j;
                __half2 s0 = __float2half2_rn(e0p[j]);
                __half2 s1 = __float2half2_rn(e1p[j]);
                x0 = __hfma2(s0, wh[k][0], x0);
                x1 = __hfma2(s0, wh[k][1], x1);
                x2 = __hfma2(s0, wh[k][2], x2);
                x3 = __hfma2(s0, wh[k][3], x3);
                y0 = __hfma2(s1, wh[k][0], y0);
                y1 = __hfma2(s1, wh[k][1], y1);
                y2 = __hfma2(s1, wh[k][2], y2);
                y3 = __hfma2(s1, wh[k][3], y3);
            }
        }
        if (hasNext) asm volatile("cp.async.wait_group 1;");
        else         asm volatile("cp.async.wait_group 0;");
        __syncwarp();
        float4 p1a0 = sP[buf][0][tid];
        float4 p1b0 = sP[buf][1][tid];
        float4 p2a0 = sP[buf][2][tid];
        float4 p2b0 = sP[buf][3][tid];
        float4 p1a1 = sP[buf][4][tid];
        float4 p1b1 = sP[buf][5][tid];
        float4 p2a1 = sP[buf][6][tid];
        float4 p2b1 = sP[buf][7][tid];
        float2 f0v = __half22float2(x0), f1v = __half22float2(x1);
        float2 f2v = __half22float2(x2), f3v = __half22float2(x3);
        float2 g0v = __half22float2(y0), g1v = __half22float2(y1);
        float2 g2v = __half22float2(y2), g3v = __half22float2(y3);
        float acc0 =
              eluf(f0v.x + p1a0.x + p2a0.x + b0.x) * c20.x
            + eluf(f0v.y + p1a0.y + p2a0.y + b0.y) * c20.y
            + eluf(f1v.x + p1a0.z + p2a0.z + b0.z) * c20.z
            + eluf(f1v.y + p1a0.w + p2a0.w + b0.w) * c20.w
            + eluf(f2v.x + p1b0.x + p2b0.x + b1.x) * c21.x
            + eluf(f2v.y + p1b0.y + p2b0.y + b1.y) * c21.y
            + eluf(f3v.x + p1b0.z + p2b0.z + b1.z) * c21.z
            + eluf(f3v.y + p1b0.w + p2b0.w + b1.w) * c21.w;
        float acc1 =
              eluf(g0v.x + p1a1.x + p2a1.x + b0.x) * c20.x
            + eluf(g0v.y + p1a1.y + p2a1.y + b0.y) * c20.y
            + eluf(g1v.x + p1a1.z + p2a1.z + b0.z) * c20.z
            + eluf(g1v.y + p1a1.w + p2a1.w + b0.w) * c20.w
            + eluf(g2v.x + p1b1.x + p2b1.x + b1.x) * c21.x
            + eluf(g2v.y + p1b1.y + p2b1.y + b1.y) * c21.y
            + eluf(g3v.x + p1b1.z + p2b1.z + b1.z) * c21.z
            + eluf(g3v.y + p1b1.w + p2b1.w + b1.w) * c21.w;
        #pragma unroll
        for (int o = 16; o; o >>= 1) {
            acc0 += __shfl_xor_sync(0xffffffffu, acc0, o);
            acc1 += __shfl_xor_sync(0xffffffffu, acc1, o);
        }
        if (lane == 0) {
            out[e0] = acc0 + cb2;
            out[e1] = acc1 + cb2;
        }
        buf ^= 1;
    }
}

// ---------------- host orchestration ----------------------------------------
static inline int ceil_div(int a, int b) { return (a + b - 1) / b; }

extern "C" void kernel_launch(void* const* d_in, const int* in_sizes, int n_in,
                              void* d_out, int out_size) {
    const float* x     = (const float*)d_in[0];
    const float* eattr = (const float*)d_in[1];
    const float* W1l   = (const float*)d_in[2];
    const float* b1l   = (const float*)d_in[3];
    const float* W1r   = (const float*)d_in[4];
    const float* b1r   = (const float*)d_in[5];
    const float* We1   = (const float*)d_in[6];
    const float* att1  = (const float*)d_in[7];
    const float* bias1 = (const float*)d_in[8];
    const float* W2l   = (const float*)d_in[9];
    const float* b2l   = (const float*)d_in[10];
    const float* W2r   = (const float*)d_in[11];
    const float* b2r   = (const float*)d_in[12];
    const float* We2   = (const float*)d_in[13];
    const float* att2  = (const float*)d_in[14];
    const float* bias2 = (const float*)d_in[15];
    // d_in[16..19] (Aw1/Ab1/Aw2/Ab2): softmax over a single column == 1 -> unused
    const float* Cw1   = (const float*)d_in[20];
    const float* Cb1   = (const float*)d_in[21];
    const float* Cw2   = (const float*)d_in[22];
    const float* Cb2   = (const float*)d_in[23];
    const int*   ei    = (const int*)  d_in[24];
    float* out = (float*)d_out;

    float *d_h, *d_h2, *d_P12, *d_Wp2, *d_WpC, *d_bp2, *d_xlr;
    __half *d_ewe1, *d_ewe2;
    cudaGetSymbolAddress((void**)&d_h,    g_h);
    cudaGetSymbolAddress((void**)&d_h2,   g_h2);
    cudaGetSymbolAddress((void**)&d_P12,  g_P12);
    cudaGetSymbolAddress((void**)&d_Wp2,  g_Wp2);
    cudaGetSymbolAddress((void**)&d_WpC,  g_WpC);
    cudaGetSymbolAddress((void**)&d_bp2,  g_bp2);
    cudaGetSymbolAddress((void**)&d_xlr,  g_xlr);
    cudaGetSymbolAddress((void**)&d_ewe1, g_ewe1);
    cudaGetSymbolAddress((void**)&d_ewe2, g_ewe2);

    const int TB = 256;
    int gatBlocks = ceil_div(NN * 32, TB);

    // 1: pack weights + histogram
    prep_kernel<<<ceil_div(EE, TB), TB>>>(W1l, W1r, b1l, b1r, W2l, W2r, b2l, b2r,
                                          We1, We2, Cw1, ei);
    // 2-3: parallel scan (block sums + offsets)
    scan_blocksum_kernel<<<SCAN_BLOCKS, 1024>>>();
    scan_offsets_kernel<<<1, 64>>>(SCAN_BLOCKS);
    // 4: ewe GEMM (independent of scan)  (ncu capture slot)
    ewe_kernel<<<EWE_BLOCKS, 256>>>(eattr);
    // 5: scan finalize (+ re-zero g_cnt)
    scan_final_kernel<<<SCAN_BLOCKS, 1024>>>();
    // 6: CSR scatter + layer-1 GEMM fused
    scatter_gemm_kernel<<<SCAT_BLOCKS + 2 * ROW_BLOCKS, 256>>>(ei, x);
    // 7: GAT layer 1
    gat_layer_kernel<<<gatBlocks, TB>>>(d_ewe1, att1, bias1, d_h, 1);
    // 8-9: layer 2
    gemm_tf32_kernel<<<dim3(ROW_BLOCKS, 2), 256>>>(d_h, d_Wp2, d_bp2, d_xlr, NN, C, 128);
    gat_layer_kernel<<<gatBlocks, TB>>>(d_ewe2, att2, bias2, d_h2, 0);
    // 10-11: classifier
    gemm_tf32_kernel<<<dim3(ROW_BLOCKS, 8), 256>>>(d_h2, d_WpC, nullptr, d_P12, NN, C, 512);
    classifier_kernel<<<2368, 128>>>(eattr, ei, Cw1 + 2 * C * HID, Cb1, Cw2, Cb2, out);
}